// round 3
// baseline (speedup 1.0000x reference)
#include <cuda_runtime.h>
#include <math.h>

// ---------------------------------------------------------------------------
// Problem constants (fixed instance)
// ---------------------------------------------------------------------------
constexpr int Bc  = 2;
constexpr int Cc  = 256;
constexpr int NHc = 8;
constexpr int Lc  = 4;
constexpr int Pc  = 4;
constexpr int Dc  = 32;          // C / NH
constexpr int LVc = 13294;       // 100*100 + 50*50 + 25*25 + 13*13
constexpr int LQc = 13294;
constexpr int Mrows = Bc * LQc;  // 26588
constexpr int PROJW = NHc * Lc * Pc * 2 + NHc * Lc * Pc; // 256 + 128 = 384

// Scratch (device globals; no allocation allowed)
__device__ float g_val [Bc * LVc * Cc];     // [b][lv][c]         ~27 MB
__device__ float g_proj[Bc * LQc * PROJW];  // [b][q][384]        ~41 MB
__device__ float g_msda[Bc * LQc * Cc];     // [b][q][c]          ~27 MB

// ---------------------------------------------------------------------------
// Packed f32x2 helpers (sm_103a FFMA2 — 2 fp32 FMAs per fma-pipe slot)
// ---------------------------------------------------------------------------
__device__ __forceinline__ unsigned long long dup2(float v) {
    unsigned long long r;
    asm("mov.b64 %0, {%1, %1};" : "=l"(r) : "f"(v));
    return r;
}
__device__ __forceinline__ void ffma2(unsigned long long& d,
                                      unsigned long long a,
                                      unsigned long long b) {
    asm("fma.rn.f32x2 %0, %1, %2, %0;" : "+l"(d) : "l"(a), "l"(b));
}
__device__ __forceinline__ void unpack2(unsigned long long v, float& lo, float& hi) {
    asm("mov.b64 {%0, %1}, %2;" : "=f"(lo), "=f"(hi) : "l"(v));
}

// ---------------------------------------------------------------------------
// Tiled FP32 GEMM via FFMA2:  Cout = A(MxK=256) * W(256xN) + bias (+ residual)
//   A_ILV:   A row m decomposes m = b*Lseq + s, element at A[(s*Bc+b)*256 + k]
//   OUT_MODE 0: Cout[m*ldc + n]
//   OUT_MODE 1: Cout[(s*Bc+b)*256 + n] += resid
// Tiles: BM=128, BN=128, BK=16, 256 threads, 8x8 microtile (as 8x4 f32x2),
// 2-stage smem double buffering.
// ---------------------------------------------------------------------------
template<bool A_ILV, int OUT_MODE>
__global__ __launch_bounds__(256)
void sgemm(const float* __restrict__ A, const float* __restrict__ W,
           const float* __restrict__ bias, float* __restrict__ Cout,
           int M, int Lseq, int ldw, int ldc,
           const float* __restrict__ resid)
{
    __shared__ float As[2][16][132];   // [stage][k][row]
    __shared__ float Ws[2][16][132];   // [stage][k][col]

    const int tid = threadIdx.x;
    const int tx = tid & 15;        // 0..15 -> 8 cols
    const int ty = tid >> 4;        // 0..15 -> 8 rows
    const int m0 = blockIdx.x * 128;
    const int n0 = blockIdx.y * 128;

    // A-tile load slots (2 float4 per k-tile)
    int arow[2], ac[2];
    const float* aptr[2];
    #pragma unroll
    for (int r = 0; r < 2; r++) {
        int idx = tid + r * 256;            // 0..511 float4 slots (128 rows x 4)
        arow[r] = idx >> 2;
        ac[r]   = (idx & 3) * 4;
        int m = m0 + arow[r];
        if (m < M) {
            int off;
            if (A_ILV) { int b = m / Lseq; int s = m - b * Lseq;
                         off = (s * Bc + b) * Cc; }
            else       { off = m * Cc; }
            aptr[r] = A + off;
        } else {
            aptr[r] = nullptr;
        }
    }
    // W-tile load slots (2 float4 per k-tile): 16 rows x 32 float4
    int wk[2], wc[2];
    #pragma unroll
    for (int r = 0; r < 2; r++) {
        int idx = tid + r * 256;
        wk[r] = idx >> 5;
        wc[r] = (idx & 31) * 4;
    }
    const float* wbase = W + n0;

    unsigned long long acc[8][4];
    #pragma unroll
    for (int i = 0; i < 8; i++)
        #pragma unroll
        for (int j = 0; j < 4; j++) acc[i][j] = 0ull;

    const float4 f4z = make_float4(0.f, 0.f, 0.f, 0.f);

    // Prologue: load k-tile 0 and stage it
    float4 na[2], nw[2];
    #pragma unroll
    for (int r = 0; r < 2; r++) {
        na[r] = aptr[r] ? *(const float4*)(aptr[r] + ac[r]) : f4z;
        nw[r] = *(const float4*)(wbase + wk[r] * ldw + wc[r]);
    }
    #pragma unroll
    for (int r = 0; r < 2; r++) {
        As[0][ac[r] + 0][arow[r]] = na[r].x;
        As[0][ac[r] + 1][arow[r]] = na[r].y;
        As[0][ac[r] + 2][arow[r]] = na[r].z;
        As[0][ac[r] + 3][arow[r]] = na[r].w;
        *(float4*)&Ws[0][wk[r]][wc[r]] = nw[r];
    }
    __syncthreads();

    #pragma unroll 1
    for (int kk = 0; kk < Cc / 16; kk++) {
        const int cur = kk & 1;

        // Prefetch next k-tile into registers (latency hidden by compute)
        if (kk < Cc / 16 - 1) {
            const int kb = (kk + 1) * 16;
            #pragma unroll
            for (int r = 0; r < 2; r++) {
                na[r] = aptr[r] ? *(const float4*)(aptr[r] + kb + ac[r]) : f4z;
                nw[r] = *(const float4*)(wbase + (kb + wk[r]) * ldw + wc[r]);
            }
        }

        const float (*Asc)[132] = As[cur];
        const float (*Wsc)[132] = Ws[cur];
        #pragma unroll
        for (int k = 0; k < 16; k++) {
            float4 a0 = *(const float4*)&Asc[k][ty * 8];
            float4 a1 = *(const float4*)&Asc[k][ty * 8 + 4];
            ulonglong2 b01 = *(const ulonglong2*)&Wsc[k][tx * 8];
            ulonglong2 b23 = *(const ulonglong2*)&Wsc[k][tx * 8 + 4];
            unsigned long long bd[4] = {b01.x, b01.y, b23.x, b23.y};
            float av[8] = {a0.x, a0.y, a0.z, a0.w, a1.x, a1.y, a1.z, a1.w};
            #pragma unroll
            for (int i = 0; i < 8; i++) {
                unsigned long long ad = dup2(av[i]);
                ffma2(acc[i][0], ad, bd[0]);
                ffma2(acc[i][1], ad, bd[1]);
                ffma2(acc[i][2], ad, bd[2]);
                ffma2(acc[i][3], ad, bd[3]);
            }
        }

        if (kk < Cc / 16 - 1) {
            const int nxt = cur ^ 1;
            #pragma unroll
            for (int r = 0; r < 2; r++) {
                As[nxt][ac[r] + 0][arow[r]] = na[r].x;
                As[nxt][ac[r] + 1][arow[r]] = na[r].y;
                As[nxt][ac[r] + 2][arow[r]] = na[r].z;
                As[nxt][ac[r] + 3][arow[r]] = na[r].w;
                *(float4*)&Ws[nxt][wk[r]][wc[r]] = nw[r];
            }
            __syncthreads();
        }
    }

    // Bias for this thread's 8 columns
    float4 bb0 = *(const float4*)&bias[n0 + tx * 8];
    float4 bb1 = *(const float4*)&bias[n0 + tx * 8 + 4];
    float bvals[8] = {bb0.x, bb0.y, bb0.z, bb0.w, bb1.x, bb1.y, bb1.z, bb1.w};

    #pragma unroll
    for (int i = 0; i < 8; i++) {
        int m = m0 + ty * 8 + i;
        if (m >= M) continue;
        int obase;
        if (OUT_MODE == 1) {
            int b = m / Lseq; int s = m - b * Lseq;
            obase = (s * Bc + b) * Cc;
        } else {
            obase = m * ldc;
        }
        float v[8];
        #pragma unroll
        for (int j = 0; j < 4; j++) {
            unpack2(acc[i][j], v[2 * j], v[2 * j + 1]);
        }
        #pragma unroll
        for (int j = 0; j < 8; j++) v[j] += bvals[j];
        if (OUT_MODE == 1) {
            const float4* rp0 = (const float4*)&resid[obase + n0 + tx * 8];
            float4 r0 = rp0[0], r1 = rp0[1];
            v[0] += r0.x; v[1] += r0.y; v[2] += r0.z; v[3] += r0.w;
            v[4] += r1.x; v[5] += r1.y; v[6] += r1.z; v[7] += r1.w;
        }
        float4* op = (float4*)&Cout[obase + n0 + tx * 8];
        op[0] = make_float4(v[0], v[1], v[2], v[3]);
        op[1] = make_float4(v[4], v[5], v[6], v[7]);
    }
}

// ---------------------------------------------------------------------------
// Fused softmax + bilinear sampling, vectorized (unchanged from R2: 111us).
// One block per (b,q). 8 warps = 8 heads.
// Lane decomposition: g = lane>>3 (point within level), cq = lane&7 (channel
// quad, float4 covers channels cq*4..cq*4+3).
// ---------------------------------------------------------------------------
__global__ __launch_bounds__(256)
void msda_sample(const float* __restrict__ rp,
                 const float* __restrict__ val,
                 const float* __restrict__ proj,
                 float* __restrict__ msda)
{
    const int bq   = blockIdx.x;            // b*LQ + q
    const int tid  = threadIdx.x;
    const int h    = tid >> 5;
    const int lane = tid & 31;
    const int g    = lane >> 3;             // point p = g
    const int cq   = lane & 7;              // channel quad
    const int b    = bq / LQc;

    __shared__ float proj_s[PROJW];
    __shared__ float rp_s[Lc * 2];
    const float* prow = proj + bq * PROJW;
    proj_s[tid] = prow[tid];
    if (tid < 128) proj_s[256 + tid] = prow[256 + tid];
    if (tid < Lc * 2) rp_s[tid] = rp[bq * Lc * 2 + tid];
    __syncthreads();

    // Softmax over the 16 (L*P) logits of this head (lanes 0..15 hold them)
    float lg = (lane < 16) ? proj_s[256 + h * 16 + lane] : -1e30f;
    float mx = lg;
    #pragma unroll
    for (int o = 8; o > 0; o >>= 1)
        mx = fmaxf(mx, __shfl_xor_sync(0xffffffffu, mx, o));
    float e = (lane < 16) ? __expf(lg - mx) : 0.f;
    float sum = e;
    #pragma unroll
    for (int o = 8; o > 0; o >>= 1)
        sum += __shfl_xor_sync(0xffffffffu, sum, o);
    float attn_val = e / sum;   // valid for lanes 0..15

    constexpr int   HH[4] = {100, 50, 25, 13};
    constexpr int   ST[4] = {0, 10000, 12500, 13125};

    // float4 base: val[b][.][h*32 + cq*4]
    const float4* vb = (const float4*)val + (b * LVc) * (Cc / 4) + h * 8 + cq;

    float4 acc = make_float4(0.f, 0.f, 0.f, 0.f);

    #pragma unroll
    for (int l = 0; l < Lc; l++) {
        const int   Wl = HH[l];
        const int   st = ST[l];
        const float fW = (float)HH[l];
        float rpx = fminf(fmaxf(rp_s[l * 2 + 0], 1e-5f), 1.f - 1e-5f);
        float rpy = fminf(fmaxf(rp_s[l * 2 + 1], 1e-5f), 1.f - 1e-5f);

        const int j = ((h * Lc + l) * Pc + g) * 2;
        float offx = proj_s[j];
        float offy = proj_s[j + 1];

        // x = (rp + off/W)*W - 0.5 = rp*W + off - 0.5   (square levels: H==W)
        float x = fmaf(rpx, fW, offx) - 0.5f;
        float y = fmaf(rpy, fW, offy) - 0.5f;
        float x0f = floorf(x), y0f = floorf(y);
        int x0 = (int)x0f, y0 = (int)y0f;
        float wx = x - x0f, wy = y - y0f;

        float a = __shfl_sync(0xffffffffu, attn_val, l * 4 + g);

        float w00 = a * (1.f - wy) * (1.f - wx);
        float w01 = a * (1.f - wy) * wx;
        float w10 = a * wy * (1.f - wx);
        float w11 = a * wy * wx;

        int x1 = x0 + 1, y1 = y0 + 1;
        bool vx0 = (x0 >= 0) & (x0 < Wl);
        bool vx1 = (x1 >= 0) & (x1 < Wl);
        bool vy0 = (y0 >= 0) & (y0 < Wl);
        bool vy1 = (y1 >= 0) & (y1 < Wl);

        int row0 = (st + y0 * Wl) * (Cc / 4);
        int row1 = row0 + Wl * (Cc / 4);

        if (vy0 & vx0) {
            float4 v = vb[row0 + x0 * (Cc / 4)];
            acc.x = fmaf(w00, v.x, acc.x); acc.y = fmaf(w00, v.y, acc.y);
            acc.z = fmaf(w00, v.z, acc.z); acc.w = fmaf(w00, v.w, acc.w);
        }
        if (vy0 & vx1) {
            float4 v = vb[row0 + x1 * (Cc / 4)];
            acc.x = fmaf(w01, v.x, acc.x); acc.y = fmaf(w01, v.y, acc.y);
            acc.z = fmaf(w01, v.z, acc.z); acc.w = fmaf(w01, v.w, acc.w);
        }
        if (vy1 & vx0) {
            float4 v = vb[row1 + x0 * (Cc / 4)];
            acc.x = fmaf(w10, v.x, acc.x); acc.y = fmaf(w10, v.y, acc.y);
            acc.z = fmaf(w10, v.z, acc.z); acc.w = fmaf(w10, v.w, acc.w);
        }
        if (vy1 & vx1) {
            float4 v = vb[row1 + x1 * (Cc / 4)];
            acc.x = fmaf(w11, v.x, acc.x); acc.y = fmaf(w11, v.y, acc.y);
            acc.z = fmaf(w11, v.z, acc.z); acc.w = fmaf(w11, v.w, acc.w);
        }
    }

    // Reduce across the 4 point-groups (lanes differing in bits 3,4)
    #pragma unroll
    for (int o = 8; o <= 16; o <<= 1) {
        acc.x += __shfl_xor_sync(0xffffffffu, acc.x, o);
        acc.y += __shfl_xor_sync(0xffffffffu, acc.y, o);
        acc.z += __shfl_xor_sync(0xffffffffu, acc.z, o);
        acc.w += __shfl_xor_sync(0xffffffffu, acc.w, o);
    }

    if (g == 0) {
        ((float4*)msda)[bq * (Cc / 4) + h * 8 + cq] = acc;
    }
}

// ---------------------------------------------------------------------------
extern "C" void kernel_launch(void* const* d_in, const int* in_sizes, int n_in,
                              void* d_out, int out_size)
{
    const float* query = (const float*)d_in[0];   // (LQ, B, C)
    const float* rp    = (const float*)d_in[1];   // (B, LQ, L, 2)
    const float* value = (const float*)d_in[2];   // (LV, B, C)
    const float* Wv    = (const float*)d_in[5];
    const float* bv    = (const float*)d_in[6];
    const float* Woff  = (const float*)d_in[7];
    const float* boff  = (const float*)d_in[8];
    const float* Wattn = (const float*)d_in[9];
    const float* battn = (const float*)d_in[10];
    const float* Wo    = (const float*)d_in[11];
    const float* bo    = (const float*)d_in[12];
    float* out = (float*)d_out;

    float *valp, *projp, *msdap;
    cudaGetSymbolAddress((void**)&valp,  g_val);
    cudaGetSymbolAddress((void**)&projp, g_proj);
    cudaGetSymbolAddress((void**)&msdap, g_msda);

    const int gm = (Mrows + 127) / 128;   // 208

    // 1) value projection: g_val[b][lv][c] = value @ Wv + bv
    sgemm<true, 0><<<dim3(gm, 2), 256>>>(value, Wv, bv, valp,
                                         Mrows, LVc, 256, 256, nullptr);
    // 2) offset projection -> g_proj[:, 0:256]
    sgemm<true, 0><<<dim3(gm, 2), 256>>>(query, Woff, boff, projp,
                                         Mrows, LQc, 256, PROJW, nullptr);
    // 3) attention logits -> g_proj[:, 256:384]
    sgemm<true, 0><<<dim3(gm, 1), 256>>>(query, Wattn, battn, projp + 256,
                                         Mrows, LQc, 128, PROJW, nullptr);
    // 4) softmax + bilinear sampling -> g_msda
    msda_sample<<<Mrows, 256>>>(rp, valp, projp, msdap);
    // 5) output projection + bias + residual -> d_out (LQ, B, C)
    sgemm<false, 1><<<dim3(gm, 2), 256>>>(msdap, Wo, bo, out,
                                          Mrows, LQc, 256, 256, query);
}

// round 4
// speedup vs baseline: 1.5227x; 1.5227x over previous
#include <cuda_runtime.h>
#include <math.h>
#include <stdint.h>

// ---------------------------------------------------------------------------
// Problem constants (fixed instance)
// ---------------------------------------------------------------------------
constexpr int Bc  = 2;
constexpr int Cc  = 256;
constexpr int NHc = 8;
constexpr int Lc  = 4;
constexpr int Pc  = 4;
constexpr int LVc = 13294;       // 100*100 + 50*50 + 25*25 + 13*13
constexpr int LQc = 13294;
constexpr int Mrows = Bc * LQc;  // 26588
constexpr int PROJW = NHc * Lc * Pc * 2 + NHc * Lc * Pc; // 256 + 128 = 384

// Scratch (device globals; no allocation allowed)
__device__ float g_val [Bc * LVc * Cc];     // [b][lv][c]
__device__ float g_proj[Bc * LQc * PROJW];  // [b][q][384]
__device__ float g_msda[Bc * LQc * Cc];     // [b][q][c]

// ---------------------------------------------------------------------------
// tf32 helpers
// ---------------------------------------------------------------------------
__device__ __forceinline__ uint32_t to_tf32(float x) {
    uint32_t r;
    asm("cvt.rna.tf32.f32 %0, %1;" : "=r"(r) : "f"(x));
    return r;
}
__device__ __forceinline__ void mma_tf32(float (&d)[4],
                                         const uint32_t (&a)[4],
                                         const uint32_t (&b)[2]) {
    asm("mma.sync.aligned.m16n8k8.row.col.f32.tf32.tf32.f32 "
        "{%0,%1,%2,%3}, {%4,%5,%6,%7}, {%8,%9}, {%0,%1,%2,%3};"
        : "+f"(d[0]), "+f"(d[1]), "+f"(d[2]), "+f"(d[3])
        : "r"(a[0]), "r"(a[1]), "r"(a[2]), "r"(a[3]),
          "r"(b[0]), "r"(b[1]));
}

// ---------------------------------------------------------------------------
// Tensor-core TF32 GEMM:  Cout = A(MxK=256) * W(256xN) + bias (+ residual)
//   A_ILV:   A row m decomposes m = b*Lseq + s, element at A[(s*Bc+b)*256 + k]
//   OUT_MODE 0: Cout[m*ldc + n]
//   OUT_MODE 1: Cout[(s*Bc+b)*256 + n] += resid
// Tiles: BM=128, BN=128, BK=16. 8 warps (2x4), warp tile 64x32,
// 4x4 m16n8k8 MMA tiles per warp. Double-buffered smem, register prefetch.
// Smem: A[m][k] pad20, B transposed [n][k] pad20 (conflict-free frag loads).
// ---------------------------------------------------------------------------
template<bool A_ILV, int OUT_MODE>
__global__ __launch_bounds__(256)
void sgemm_tc(const float* __restrict__ A, const float* __restrict__ W,
              const float* __restrict__ bias, float* __restrict__ Cout,
              int M, int Lseq, int ldw, int ldc,
              const float* __restrict__ resid)
{
    __shared__ uint32_t As[2][128][20];   // [stage][m][k]
    __shared__ uint32_t Ws[2][128][20];   // [stage][n][k]

    const int tid  = threadIdx.x;
    const int warp = tid >> 5;
    const int lane = tid & 31;
    const int wm = warp >> 2;          // 0..1 : 64-row slab
    const int wn = warp & 3;           // 0..3 : 32-col slab
    const int m0 = blockIdx.x * 128;
    const int n0 = blockIdx.y * 128;

    const int qr = lane >> 2;          // 0..7  (fragment row group)
    const int qc = lane & 3;           // 0..3  (fragment col group)

    // ---- staging slots ----
    // A: 512 float4 slots (128 rows x 4), 2 per thread
    int arow[2], ac[2];
    const float* aptr[2];
    #pragma unroll
    for (int r = 0; r < 2; r++) {
        int idx = tid + r * 256;
        arow[r] = idx >> 2;
        ac[r]   = (idx & 3) * 4;
        int m = m0 + arow[r];
        if (m < M) {
            int off;
            if (A_ILV) { int b = m / Lseq; int s = m - b * Lseq;
                         off = (s * Bc + b) * Cc; }
            else       { off = m * Cc; }
            aptr[r] = A + off;
        } else {
            aptr[r] = nullptr;
        }
    }
    // W: 512 float4 slots (16 k-rows x 32 float4 along n), 2 per thread
    int wk[2], wn4[2];
    #pragma unroll
    for (int r = 0; r < 2; r++) {
        int idx = tid + r * 256;
        wk[r]  = idx >> 5;
        wn4[r] = (idx & 31) * 4;
    }
    const float* wbase = W + n0;

    float acc[4][4][4];
    #pragma unroll
    for (int mt = 0; mt < 4; mt++)
        #pragma unroll
        for (int nt = 0; nt < 4; nt++)
            #pragma unroll
            for (int c = 0; c < 4; c++) acc[mt][nt][c] = 0.f;

    const float4 f4z = make_float4(0.f, 0.f, 0.f, 0.f);

    // ---- prologue: stage k-tile 0 ----
    float4 na[2], nw[2];
    #pragma unroll
    for (int r = 0; r < 2; r++) {
        na[r] = aptr[r] ? *(const float4*)(aptr[r] + ac[r]) : f4z;
        nw[r] = *(const float4*)(wbase + wk[r] * ldw + wn4[r]);
    }
    #pragma unroll
    for (int r = 0; r < 2; r++) {
        uint4 a4 = make_uint4(to_tf32(na[r].x), to_tf32(na[r].y),
                              to_tf32(na[r].z), to_tf32(na[r].w));
        *(uint4*)&As[0][arow[r]][ac[r]] = a4;
        Ws[0][wn4[r] + 0][wk[r]] = to_tf32(nw[r].x);
        Ws[0][wn4[r] + 1][wk[r]] = to_tf32(nw[r].y);
        Ws[0][wn4[r] + 2][wk[r]] = to_tf32(nw[r].z);
        Ws[0][wn4[r] + 3][wk[r]] = to_tf32(nw[r].w);
    }
    __syncthreads();

    #pragma unroll 1
    for (int kk = 0; kk < Cc / 16; kk++) {
        const int cur = kk & 1;

        // prefetch next k-tile into registers
        if (kk < Cc / 16 - 1) {
            const int kb = (kk + 1) * 16;
            #pragma unroll
            for (int r = 0; r < 2; r++) {
                na[r] = aptr[r] ? *(const float4*)(aptr[r] + kb + ac[r]) : f4z;
                nw[r] = *(const float4*)(wbase + (kb + wk[r]) * ldw + wn4[r]);
            }
        }

        // ---- compute on current tile: 2 k-steps of 8 ----
        #pragma unroll
        for (int ks = 0; ks < 16; ks += 8) {
            uint32_t afr[4][4];
            #pragma unroll
            for (int mt = 0; mt < 4; mt++) {
                int row = wm * 64 + mt * 16 + qr;
                afr[mt][0] = As[cur][row    ][ks + qc    ];
                afr[mt][1] = As[cur][row + 8][ks + qc    ];
                afr[mt][2] = As[cur][row    ][ks + qc + 4];
                afr[mt][3] = As[cur][row + 8][ks + qc + 4];
            }
            uint32_t bfr[4][2];
            #pragma unroll
            for (int nt = 0; nt < 4; nt++) {
                int col = wn * 32 + nt * 8 + qr;
                bfr[nt][0] = Ws[cur][col][ks + qc    ];
                bfr[nt][1] = Ws[cur][col][ks + qc + 4];
            }
            #pragma unroll
            for (int mt = 0; mt < 4; mt++)
                #pragma unroll
                for (int nt = 0; nt < 4; nt++)
                    mma_tf32(acc[mt][nt], afr[mt], bfr[nt]);
        }

        // ---- stage next tile ----
        if (kk < Cc / 16 - 1) {
            const int nxt = cur ^ 1;
            #pragma unroll
            for (int r = 0; r < 2; r++) {
                uint4 a4 = make_uint4(to_tf32(na[r].x), to_tf32(na[r].y),
                                      to_tf32(na[r].z), to_tf32(na[r].w));
                *(uint4*)&As[nxt][arow[r]][ac[r]] = a4;
                Ws[nxt][wn4[r] + 0][wk[r]] = to_tf32(nw[r].x);
                Ws[nxt][wn4[r] + 1][wk[r]] = to_tf32(nw[r].y);
                Ws[nxt][wn4[r] + 2][wk[r]] = to_tf32(nw[r].z);
                Ws[nxt][wn4[r] + 3][wk[r]] = to_tf32(nw[r].w);
            }
            __syncthreads();
        }
    }

    // ---- epilogue ----
    // bias for this thread's 4 n-tiles (2 adjacent cols each)
    float2 bvals[4];
    #pragma unroll
    for (int nt = 0; nt < 4; nt++) {
        int n = n0 + wn * 32 + nt * 8 + qc * 2;
        bvals[nt] = *(const float2*)&bias[n];
    }

    #pragma unroll
    for (int mt = 0; mt < 4; mt++) {
        #pragma unroll
        for (int hrow = 0; hrow < 2; hrow++) {
            int m = m0 + wm * 64 + mt * 16 + qr + hrow * 8;
            if (m >= M) continue;
            int obase;
            if (OUT_MODE == 1) {
                int b = m / Lseq; int s = m - b * Lseq;
                obase = (s * Bc + b) * Cc;
            } else {
                obase = m * ldc;
            }
            #pragma unroll
            for (int nt = 0; nt < 4; nt++) {
                int n = n0 + wn * 32 + nt * 8 + qc * 2;
                float vx = acc[mt][nt][hrow * 2 + 0] + bvals[nt].x;
                float vy = acc[mt][nt][hrow * 2 + 1] + bvals[nt].y;
                if (OUT_MODE == 1) {
                    float2 rr = *(const float2*)&resid[obase + n];
                    vx += rr.x; vy += rr.y;
                }
                *(float2*)&Cout[obase + n] = make_float2(vx, vy);
            }
        }
    }
}

// ---------------------------------------------------------------------------
// Fused softmax + bilinear sampling, vectorized (verified at 111us).
// One block per (b,q). 8 warps = 8 heads.
// ---------------------------------------------------------------------------
__global__ __launch_bounds__(256)
void msda_sample(const float* __restrict__ rp,
                 const float* __restrict__ val,
                 const float* __restrict__ proj,
                 float* __restrict__ msda)
{
    const int bq   = blockIdx.x;            // b*LQ + q
    const int tid  = threadIdx.x;
    const int h    = tid >> 5;
    const int lane = tid & 31;
    const int g    = lane >> 3;             // point p = g
    const int cq   = lane & 7;              // channel quad
    const int b    = bq / LQc;

    __shared__ float proj_s[PROJW];
    __shared__ float rp_s[Lc * 2];
    const float* prow = proj + bq * PROJW;
    proj_s[tid] = prow[tid];
    if (tid < 128) proj_s[256 + tid] = prow[256 + tid];
    if (tid < Lc * 2) rp_s[tid] = rp[bq * Lc * 2 + tid];
    __syncthreads();

    float lg = (lane < 16) ? proj_s[256 + h * 16 + lane] : -1e30f;
    float mx = lg;
    #pragma unroll
    for (int o = 8; o > 0; o >>= 1)
        mx = fmaxf(mx, __shfl_xor_sync(0xffffffffu, mx, o));
    float e = (lane < 16) ? __expf(lg - mx) : 0.f;
    float sum = e;
    #pragma unroll
    for (int o = 8; o > 0; o >>= 1)
        sum += __shfl_xor_sync(0xffffffffu, sum, o);
    float attn_val = e / sum;

    constexpr int HH[4] = {100, 50, 25, 13};
    constexpr int ST[4] = {0, 10000, 12500, 13125};

    const float4* vb = (const float4*)val + (b * LVc) * (Cc / 4) + h * 8 + cq;

    float4 acc = make_float4(0.f, 0.f, 0.f, 0.f);

    #pragma unroll
    for (int l = 0; l < Lc; l++) {
        const int   Wl = HH[l];
        const int   st = ST[l];
        const float fW = (float)HH[l];
        float rpx = fminf(fmaxf(rp_s[l * 2 + 0], 1e-5f), 1.f - 1e-5f);
        float rpy = fminf(fmaxf(rp_s[l * 2 + 1], 1e-5f), 1.f - 1e-5f);

        const int j = ((h * Lc + l) * Pc + g) * 2;
        float offx = proj_s[j];
        float offy = proj_s[j + 1];

        float x = fmaf(rpx, fW, offx) - 0.5f;
        float y = fmaf(rpy, fW, offy) - 0.5f;
        float x0f = floorf(x), y0f = floorf(y);
        int x0 = (int)x0f, y0 = (int)y0f;
        float wx = x - x0f, wy = y - y0f;

        float a = __shfl_sync(0xffffffffu, attn_val, l * 4 + g);

        float w00 = a * (1.f - wy) * (1.f - wx);
        float w01 = a * (1.f - wy) * wx;
        float w10 = a * wy * (1.f - wx);
        float w11 = a * wy * wx;

        int x1 = x0 + 1, y1 = y0 + 1;
        bool vx0 = (x0 >= 0) & (x0 < Wl);
        bool vx1 = (x1 >= 0) & (x1 < Wl);
        bool vy0 = (y0 >= 0) & (y0 < Wl);
        bool vy1 = (y1 >= 0) & (y1 < Wl);

        int row0 = (st + y0 * Wl) * (Cc / 4);
        int row1 = row0 + Wl * (Cc / 4);

        if (vy0 & vx0) {
            float4 v = vb[row0 + x0 * (Cc / 4)];
            acc.x = fmaf(w00, v.x, acc.x); acc.y = fmaf(w00, v.y, acc.y);
            acc.z = fmaf(w00, v.z, acc.z); acc.w = fmaf(w00, v.w, acc.w);
        }
        if (vy0 & vx1) {
            float4 v = vb[row0 + x1 * (Cc / 4)];
            acc.x = fmaf(w01, v.x, acc.x); acc.y = fmaf(w01, v.y, acc.y);
            acc.z = fmaf(w01, v.z, acc.z); acc.w = fmaf(w01, v.w, acc.w);
        }
        if (vy1 & vx0) {
            float4 v = vb[row1 + x0 * (Cc / 4)];
            acc.x = fmaf(w10, v.x, acc.x); acc.y = fmaf(w10, v.y, acc.y);
            acc.z = fmaf(w10, v.z, acc.z); acc.w = fmaf(w10, v.w, acc.w);
        }
        if (vy1 & vx1) {
            float4 v = vb[row1 + x1 * (Cc / 4)];
            acc.x = fmaf(w11, v.x, acc.x); acc.y = fmaf(w11, v.y, acc.y);
            acc.z = fmaf(w11, v.z, acc.z); acc.w = fmaf(w11, v.w, acc.w);
        }
    }

    #pragma unroll
    for (int o = 8; o <= 16; o <<= 1) {
        acc.x += __shfl_xor_sync(0xffffffffu, acc.x, o);
        acc.y += __shfl_xor_sync(0xffffffffu, acc.y, o);
        acc.z += __shfl_xor_sync(0xffffffffu, acc.z, o);
        acc.w += __shfl_xor_sync(0xffffffffu, acc.w, o);
    }

    if (g == 0) {
        ((float4*)msda)[bq * (Cc / 4) + h * 8 + cq] = acc;
    }
}

// ---------------------------------------------------------------------------
extern "C" void kernel_launch(void* const* d_in, const int* in_sizes, int n_in,
                              void* d_out, int out_size)
{
    const float* query = (const float*)d_in[0];   // (LQ, B, C)
    const float* rp    = (const float*)d_in[1];   // (B, LQ, L, 2)
    const float* value = (const float*)d_in[2];   // (LV, B, C)
    const float* Wv    = (const float*)d_in[5];
    const float* bv    = (const float*)d_in[6];
    const float* Woff  = (const float*)d_in[7];
    const float* boff  = (const float*)d_in[8];
    const float* Wattn = (const float*)d_in[9];
    const float* battn = (const float*)d_in[10];
    const float* Wo    = (const float*)d_in[11];
    const float* bo    = (const float*)d_in[12];
    float* out = (float*)d_out;

    float *valp, *projp, *msdap;
    cudaGetSymbolAddress((void**)&valp,  g_val);
    cudaGetSymbolAddress((void**)&projp, g_proj);
    cudaGetSymbolAddress((void**)&msdap, g_msda);

    const int gm = (Mrows + 127) / 128;   // 208

    // 1) value projection
    sgemm_tc<true, 0><<<dim3(gm, 2), 256>>>(value, Wv, bv, valp,
                                            Mrows, LVc, 256, 256, nullptr);
    // 2) offset projection -> g_proj[:, 0:256]
    sgemm_tc<true, 0><<<dim3(gm, 2), 256>>>(query, Woff, boff, projp,
                                            Mrows, LQc, 256, PROJW, nullptr);
    // 3) attention logits -> g_proj[:, 256:384]
    sgemm_tc<true, 0><<<dim3(gm, 1), 256>>>(query, Wattn, battn, projp + 256,
                                            Mrows, LQc, 128, PROJW, nullptr);
    // 4) softmax + bilinear sampling -> g_msda
    msda_sample<<<Mrows, 256>>>(rp, valp, projp, msdap);
    // 5) output projection + bias + residual -> d_out (LQ, B, C)
    sgemm_tc<false, 1><<<dim3(gm, 2), 256>>>(msdap, Wo, bo, out,
                                             Mrows, LQc, 256, 256, query);
}

// round 5
// speedup vs baseline: 1.9145x; 1.2573x over previous
#include <cuda_runtime.h>
#include <math.h>
#include <stdint.h>

// ---------------------------------------------------------------------------
// Problem constants (fixed instance)
// ---------------------------------------------------------------------------
constexpr int Bc  = 2;
constexpr int Cc  = 256;
constexpr int NHc = 8;
constexpr int Lc  = 4;
constexpr int Pc  = 4;
constexpr int LVc = 13294;       // 100*100 + 50*50 + 25*25 + 13*13
constexpr int LQc = 13294;
constexpr int Mrows = Bc * LQc;  // 26588
constexpr int PROJW = NHc * Lc * Pc * 2 + NHc * Lc * Pc; // 256 + 128 = 384

// Scratch (device globals; no allocation allowed)
__device__ float g_val [Bc * LVc * Cc];     // [b][lv][c]
__device__ float g_proj[Bc * LQc * PROJW];  // [b][q][384]
__device__ float g_msda[Bc * LQc * Cc];     // [b][q][c]
__device__ float g_wcat[Cc * PROJW];        // Woff || Wattn  [256][384]
__device__ float g_bcat[PROJW];             // boff || battn

// ---------------------------------------------------------------------------
// tf32 helpers
// ---------------------------------------------------------------------------
__device__ __forceinline__ uint32_t to_tf32(float x) {
    uint32_t r;
    asm("cvt.rna.tf32.f32 %0, %1;" : "=r"(r) : "f"(x));
    return r;
}
__device__ __forceinline__ void mma_tf32(float (&d)[4],
                                         const uint32_t (&a)[4],
                                         const uint32_t (&b)[2]) {
    asm("mma.sync.aligned.m16n8k8.row.col.f32.tf32.tf32.f32 "
        "{%0,%1,%2,%3}, {%4,%5,%6,%7}, {%8,%9}, {%0,%1,%2,%3};"
        : "+f"(d[0]), "+f"(d[1]), "+f"(d[2]), "+f"(d[3])
        : "r"(a[0]), "r"(a[1]), "r"(a[2]), "r"(a[3]),
          "r"(b[0]), "r"(b[1]));
}

// ---------------------------------------------------------------------------
// Weight/bias concat: g_wcat[k][n] = n<256 ? Woff[k][n] : Wattn[k][n-256]
// ---------------------------------------------------------------------------
__global__ void concat_w(const float* __restrict__ Woff,
                         const float* __restrict__ boff,
                         const float* __restrict__ Wattn,
                         const float* __restrict__ battn,
                         float* __restrict__ wcat, float* __restrict__ bcat)
{
    int i = blockIdx.x * 256 + threadIdx.x;
    if (i < Cc * PROJW) {
        int k = i / PROJW, n = i - k * PROJW;
        wcat[i] = (n < 256) ? Woff[k * 256 + n] : Wattn[k * 128 + n - 256];
    }
    if (i < PROJW) bcat[i] = (i < 256) ? boff[i] : battn[i - 256];
}

// ---------------------------------------------------------------------------
// Tensor-core TF32 GEMM:  Cout = A(MxK=256) * W(256xN) + bias (+ residual)
//   A_ILV:   A row m decomposes m = b*Lseq + s, element at A[(s*Bc+b)*256 + k]
//   OUT_MODE 0: Cout[m*ldc + n]
//   OUT_MODE 1: Cout[(s*Bc+b)*256 + n] += resid
// BM=128, BN=128, BK=16. 8 warps (2x4), warp tile 64x32, 4x4 m16n8k8 tiles.
// Smem: A[m][k] pad20 (frag LDS conflict-free); B natural [k][n] pad132
// (STS.128 staging conflict-free; frag LDS <=2-way). Double-buffered.
// ---------------------------------------------------------------------------
template<bool A_ILV, int OUT_MODE>
__global__ __launch_bounds__(256)
void sgemm_tc(const float* __restrict__ A, const float* __restrict__ W,
              const float* __restrict__ bias, float* __restrict__ Cout,
              int M, int Lseq, int ldw, int ldc,
              const float* __restrict__ resid)
{
    __shared__ uint32_t As[2][128][20];   // [stage][m][k]
    __shared__ uint32_t Ws[2][16][132];   // [stage][k][n]

    const int tid  = threadIdx.x;
    const int warp = tid >> 5;
    const int lane = tid & 31;
    const int wm = warp >> 2;          // 0..1 : 64-row slab
    const int wn = warp & 3;           // 0..3 : 32-col slab
    const int m0 = blockIdx.x * 128;
    const int n0 = blockIdx.y * 128;

    const int qr = lane >> 2;          // 0..7
    const int qc = lane & 3;           // 0..3

    // ---- staging slots ----
    int arow[2], ac[2];
    const float* aptr[2];
    #pragma unroll
    for (int r = 0; r < 2; r++) {
        int idx = tid + r * 256;
        arow[r] = idx >> 2;
        ac[r]   = (idx & 3) * 4;
        int m = m0 + arow[r];
        if (m < M) {
            int off;
            if (A_ILV) { int b = m / Lseq; int s = m - b * Lseq;
                         off = (s * Bc + b) * Cc; }
            else       { off = m * Cc; }
            aptr[r] = A + off;
        } else {
            aptr[r] = nullptr;
        }
    }
    int wk[2], wn4[2];
    #pragma unroll
    for (int r = 0; r < 2; r++) {
        int idx = tid + r * 256;
        wk[r]  = idx >> 5;          // 0..15 (k row)
        wn4[r] = (idx & 31) * 4;    // 0..124 (n col)
    }
    const float* wbase = W + n0;

    float acc[4][4][4];
    #pragma unroll
    for (int mt = 0; mt < 4; mt++)
        #pragma unroll
        for (int nt = 0; nt < 4; nt++)
            #pragma unroll
            for (int c = 0; c < 4; c++) acc[mt][nt][c] = 0.f;

    const float4 f4z = make_float4(0.f, 0.f, 0.f, 0.f);

    // ---- prologue: stage k-tile 0 ----
    float4 na[2], nw[2];
    #pragma unroll
    for (int r = 0; r < 2; r++) {
        na[r] = aptr[r] ? *(const float4*)(aptr[r] + ac[r]) : f4z;
        nw[r] = *(const float4*)(wbase + wk[r] * ldw + wn4[r]);
    }
    #pragma unroll
    for (int r = 0; r < 2; r++) {
        uint4 a4 = make_uint4(to_tf32(na[r].x), to_tf32(na[r].y),
                              to_tf32(na[r].z), to_tf32(na[r].w));
        *(uint4*)&As[0][arow[r]][ac[r]] = a4;
        uint4 w4 = make_uint4(to_tf32(nw[r].x), to_tf32(nw[r].y),
                              to_tf32(nw[r].z), to_tf32(nw[r].w));
        *(uint4*)&Ws[0][wk[r]][wn4[r]] = w4;
    }
    __syncthreads();

    #pragma unroll 1
    for (int kk = 0; kk < Cc / 16; kk++) {
        const int cur = kk & 1;

        // prefetch next k-tile into registers
        if (kk < Cc / 16 - 1) {
            const int kb = (kk + 1) * 16;
            #pragma unroll
            for (int r = 0; r < 2; r++) {
                na[r] = aptr[r] ? *(const float4*)(aptr[r] + kb + ac[r]) : f4z;
                nw[r] = *(const float4*)(wbase + (kb + wk[r]) * ldw + wn4[r]);
            }
        }

        // ---- compute: 2 k-steps of 8 ----
        #pragma unroll
        for (int ks = 0; ks < 16; ks += 8) {
            uint32_t afr[4][4];
            #pragma unroll
            for (int mt = 0; mt < 4; mt++) {
                int row = wm * 64 + mt * 16 + qr;
                afr[mt][0] = As[cur][row    ][ks + qc    ];
                afr[mt][1] = As[cur][row + 8][ks + qc    ];
                afr[mt][2] = As[cur][row    ][ks + qc + 4];
                afr[mt][3] = As[cur][row + 8][ks + qc + 4];
            }
            uint32_t bfr[4][2];
            #pragma unroll
            for (int nt = 0; nt < 4; nt++) {
                int col = wn * 32 + nt * 8 + qr;
                bfr[nt][0] = Ws[cur][ks + qc    ][col];
                bfr[nt][1] = Ws[cur][ks + qc + 4][col];
            }
            #pragma unroll
            for (int mt = 0; mt < 4; mt++)
                #pragma unroll
                for (int nt = 0; nt < 4; nt++)
                    mma_tf32(acc[mt][nt], afr[mt], bfr[nt]);
        }

        // ---- stage next tile ----
        if (kk < Cc / 16 - 1) {
            const int nxt = cur ^ 1;
            #pragma unroll
            for (int r = 0; r < 2; r++) {
                uint4 a4 = make_uint4(to_tf32(na[r].x), to_tf32(na[r].y),
                                      to_tf32(na[r].z), to_tf32(na[r].w));
                *(uint4*)&As[nxt][arow[r]][ac[r]] = a4;
                uint4 w4 = make_uint4(to_tf32(nw[r].x), to_tf32(nw[r].y),
                                      to_tf32(nw[r].z), to_tf32(nw[r].w));
                *(uint4*)&Ws[nxt][wk[r]][wn4[r]] = w4;
            }
            __syncthreads();
        }
    }

    // ---- epilogue ----
    float2 bvals[4];
    #pragma unroll
    for (int nt = 0; nt < 4; nt++) {
        int n = n0 + wn * 32 + nt * 8 + qc * 2;
        bvals[nt] = *(const float2*)&bias[n];
    }

    #pragma unroll
    for (int mt = 0; mt < 4; mt++) {
        #pragma unroll
        for (int hrow = 0; hrow < 2; hrow++) {
            int m = m0 + wm * 64 + mt * 16 + qr + hrow * 8;
            if (m >= M) continue;
            int obase;
            if (OUT_MODE == 1) {
                int b = m / Lseq; int s = m - b * Lseq;
                obase = (s * Bc + b) * Cc;
            } else {
                obase = m * ldc;
            }
            #pragma unroll
            for (int nt = 0; nt < 4; nt++) {
                int n = n0 + wn * 32 + nt * 8 + qc * 2;
                float vx = acc[mt][nt][hrow * 2 + 0] + bvals[nt].x;
                float vy = acc[mt][nt][hrow * 2 + 1] + bvals[nt].y;
                if (OUT_MODE == 1) {
                    float2 rr = *(const float2*)&resid[obase + n];
                    vx += rr.x; vy += rr.y;
                }
                *(float2*)&Cout[obase + n] = make_float2(vx, vy);
            }
        }
    }
}

// ---------------------------------------------------------------------------
// Fused softmax + bilinear sampling — warp-autonomous (no smem, no barriers).
// One warp per (b,q,head). Block 512 threads = 16 warps = 2 queries.
// Lane split: g = lane>>3 (point in level), cq = lane&7 (channel quad).
// ---------------------------------------------------------------------------
__global__ __launch_bounds__(512)
void msda_sample(const float* __restrict__ rp,
                 const float* __restrict__ val,
                 const float* __restrict__ proj,
                 float* __restrict__ msda)
{
    const int gw   = (blockIdx.x * 512 + threadIdx.x) >> 5;   // global warp
    const int lane = threadIdx.x & 31;
    const int bq   = gw >> 3;
    const int h    = gw & 7;
    const int g    = lane >> 3;
    const int cq   = lane & 7;
    const int b    = bq / LQc;

    // Warp-local loads of this head's parameters
    const float* prow = proj + bq * PROJW;
    float off = prow[h * 32 + lane];                       // 32 offset scalars
    float lg  = (lane < 16) ? prow[256 + h * 16 + lane] : -1e30f;
    float rpv = (lane < 8)  ? rp[bq * (Lc * 2) + lane] : 0.f;

    // Softmax over 16 logits (lanes 0..15)
    float mx = lg;
    #pragma unroll
    for (int o = 8; o > 0; o >>= 1)
        mx = fmaxf(mx, __shfl_xor_sync(0xffffffffu, mx, o));
    float e = (lane < 16) ? __expf(lg - mx) : 0.f;
    float sum = e;
    #pragma unroll
    for (int o = 8; o > 0; o >>= 1)
        sum += __shfl_xor_sync(0xffffffffu, sum, o);
    float attn_val = e / sum;

    constexpr int HH[4] = {100, 50, 25, 13};
    constexpr int ST[4] = {0, 10000, 12500, 13125};

    const float4* vb = (const float4*)val + (b * LVc) * (Cc / 4) + h * 8 + cq;

    float4 acc = make_float4(0.f, 0.f, 0.f, 0.f);

    #pragma unroll
    for (int l = 0; l < Lc; l++) {
        const int   Wl = HH[l];
        const int   st = ST[l];
        const float fW = (float)HH[l];

        float rpx = __shfl_sync(0xffffffffu, rpv, 2 * l);
        float rpy = __shfl_sync(0xffffffffu, rpv, 2 * l + 1);
        rpx = fminf(fmaxf(rpx, 1e-5f), 1.f - 1e-5f);
        rpy = fminf(fmaxf(rpy, 1e-5f), 1.f - 1e-5f);

        float offx = __shfl_sync(0xffffffffu, off, l * 8 + 2 * g);
        float offy = __shfl_sync(0xffffffffu, off, l * 8 + 2 * g + 1);

        // x = (rp + off/W)*W - 0.5 = rp*W + off - 0.5   (square levels)
        float x = fmaf(rpx, fW, offx) - 0.5f;
        float y = fmaf(rpy, fW, offy) - 0.5f;
        float x0f = floorf(x), y0f = floorf(y);
        int x0 = (int)x0f, y0 = (int)y0f;
        float wx = x - x0f, wy = y - y0f;

        float a = __shfl_sync(0xffffffffu, attn_val, l * 4 + g);

        float w00 = a * (1.f - wy) * (1.f - wx);
        float w01 = a * (1.f - wy) * wx;
        float w10 = a * wy * (1.f - wx);
        float w11 = a * wy * wx;

        int x1 = x0 + 1, y1 = y0 + 1;
        bool vx0 = (x0 >= 0) & (x0 < Wl);
        bool vx1 = (x1 >= 0) & (x1 < Wl);
        bool vy0 = (y0 >= 0) & (y0 < Wl);
        bool vy1 = (y1 >= 0) & (y1 < Wl);

        int row0 = (st + y0 * Wl) * (Cc / 4);
        int row1 = row0 + Wl * (Cc / 4);

        if (vy0 & vx0) {
            float4 v = vb[row0 + x0 * (Cc / 4)];
            acc.x = fmaf(w00, v.x, acc.x); acc.y = fmaf(w00, v.y, acc.y);
            acc.z = fmaf(w00, v.z, acc.z); acc.w = fmaf(w00, v.w, acc.w);
        }
        if (vy0 & vx1) {
            float4 v = vb[row0 + x1 * (Cc / 4)];
            acc.x = fmaf(w01, v.x, acc.x); acc.y = fmaf(w01, v.y, acc.y);
            acc.z = fmaf(w01, v.z, acc.z); acc.w = fmaf(w01, v.w, acc.w);
        }
        if (vy1 & vx0) {
            float4 v = vb[row1 + x0 * (Cc / 4)];
            acc.x = fmaf(w10, v.x, acc.x); acc.y = fmaf(w10, v.y, acc.y);
            acc.z = fmaf(w10, v.z, acc.z); acc.w = fmaf(w10, v.w, acc.w);
        }
        if (vy1 & vx1) {
            float4 v = vb[row1 + x1 * (Cc / 4)];
            acc.x = fmaf(w11, v.x, acc.x); acc.y = fmaf(w11, v.y, acc.y);
            acc.z = fmaf(w11, v.z, acc.z); acc.w = fmaf(w11, v.w, acc.w);
        }
    }

    // Reduce across the 4 point-groups (lanes differing in bits 3,4)
    #pragma unroll
    for (int o = 8; o <= 16; o <<= 1) {
        acc.x += __shfl_xor_sync(0xffffffffu, acc.x, o);
        acc.y += __shfl_xor_sync(0xffffffffu, acc.y, o);
        acc.z += __shfl_xor_sync(0xffffffffu, acc.z, o);
        acc.w += __shfl_xor_sync(0xffffffffu, acc.w, o);
    }

    if (g == 0) {
        ((float4*)msda)[bq * (Cc / 4) + h * 8 + cq] = acc;
    }
}

// ---------------------------------------------------------------------------
extern "C" void kernel_launch(void* const* d_in, const int* in_sizes, int n_in,
                              void* d_out, int out_size)
{
    const float* query = (const float*)d_in[0];   // (LQ, B, C)
    const float* rp    = (const float*)d_in[1];   // (B, LQ, L, 2)
    const float* value = (const float*)d_in[2];   // (LV, B, C)
    const float* Wv    = (const float*)d_in[5];
    const float* bv    = (const float*)d_in[6];
    const float* Woff  = (const float*)d_in[7];
    const float* boff  = (const float*)d_in[8];
    const float* Wattn = (const float*)d_in[9];
    const float* battn = (const float*)d_in[10];
    const float* Wo    = (const float*)d_in[11];
    const float* bo    = (const float*)d_in[12];
    float* out = (float*)d_out;

    float *valp, *projp, *msdap, *wcatp, *bcatp;
    cudaGetSymbolAddress((void**)&valp,  g_val);
    cudaGetSymbolAddress((void**)&projp, g_proj);
    cudaGetSymbolAddress((void**)&msdap, g_msda);
    cudaGetSymbolAddress((void**)&wcatp, g_wcat);
    cudaGetSymbolAddress((void**)&bcatp, g_bcat);

    const int gm = (Mrows + 127) / 128;   // 208

    // 0) concat Woff||Wattn, boff||battn
    concat_w<<<(Cc * PROJW + 255) / 256, 256>>>(Woff, boff, Wattn, battn,
                                                wcatp, bcatp);
    // 1) value projection
    sgemm_tc<true, 0><<<dim3(gm, 2), 256>>>(value, Wv, bv, valp,
                                            Mrows, LVc, 256, 256, nullptr);
    // 2) fused offset+attn projection -> g_proj[:, 0:384]
    sgemm_tc<true, 0><<<dim3(gm, 3), 256>>>(query, wcatp, bcatp, projp,
                                            Mrows, LQc, PROJW, PROJW, nullptr);
    // 3) softmax + bilinear sampling -> g_msda
    msda_sample<<<Mrows / 2, 512>>>(rp, valp, projp, msdap);
    // 4) output projection + bias + residual -> d_out (LQ, B, C)
    sgemm_tc<false, 1><<<dim3(gm, 2), 256>>>(msdap, Wo, bo, out,
                                             Mrows, LQc, 256, 256, query);
}

// round 6
// speedup vs baseline: 2.3848x; 1.2456x over previous
#include <cuda_runtime.h>
#include <cuda_fp16.h>
#include <math.h>
#include <stdint.h>

// ---------------------------------------------------------------------------
// Problem constants (fixed instance)
// ---------------------------------------------------------------------------
constexpr int Bc  = 2;
constexpr int Cc  = 256;
constexpr int NHc = 8;
constexpr int Lc  = 4;
constexpr int Pc  = 4;
constexpr int LVc = 13294;       // 100*100 + 50*50 + 25*25 + 13*13
constexpr int LQc = 13294;
constexpr int Mrows = Bc * LQc;  // 26588
constexpr int PROJW = NHc * Lc * Pc * 2 + NHc * Lc * Pc; // 384

// Scratch (device globals; no allocation allowed)
__device__ __half g_val [Bc * LVc * Cc];    // [b][lv][c]  fp16
__device__ float  g_proj[Bc * LQc * PROJW]; // [b][q][384]
__device__ float  g_msda[Bc * LQc * Cc];    // [b][q][c]
__device__ float  g_wcat[Cc * PROJW];       // Woff || Wattn
__device__ float  g_bcat[PROJW];            // boff || battn

// ---------------------------------------------------------------------------
// fp16 MMA helpers
// ---------------------------------------------------------------------------
__device__ __forceinline__ uint32_t pack_h2(float a, float b) {
    __half2 h = __floats2half2_rn(a, b);
    return *reinterpret_cast<uint32_t*>(&h);
}
__device__ __forceinline__ void ldmatrix_x4(uint32_t (&r)[4], uint32_t saddr) {
    asm volatile("ldmatrix.sync.aligned.m8n8.x4.shared.b16 {%0,%1,%2,%3}, [%4];"
                 : "=r"(r[0]), "=r"(r[1]), "=r"(r[2]), "=r"(r[3])
                 : "r"(saddr));
}
__device__ __forceinline__ void mma_f16(float (&d)[4],
                                        const uint32_t (&a)[4],
                                        const uint32_t b0, const uint32_t b1) {
    asm volatile(
        "mma.sync.aligned.m16n8k16.row.col.f32.f16.f16.f32 "
        "{%0,%1,%2,%3}, {%4,%5,%6,%7}, {%8,%9}, {%0,%1,%2,%3};"
        : "+f"(d[0]), "+f"(d[1]), "+f"(d[2]), "+f"(d[3])
        : "r"(a[0]), "r"(a[1]), "r"(a[2]), "r"(a[3]), "r"(b0), "r"(b1));
}

// ---------------------------------------------------------------------------
// Weight/bias concat: g_wcat[k][n] = n<256 ? Woff[k][n] : Wattn[k][n-256]
// ---------------------------------------------------------------------------
__global__ void concat_w(const float* __restrict__ Woff,
                         const float* __restrict__ boff,
                         const float* __restrict__ Wattn,
                         const float* __restrict__ battn,
                         float* __restrict__ wcat, float* __restrict__ bcat)
{
    int i = blockIdx.x * 256 + threadIdx.x;
    if (i < Cc * PROJW) {
        int k = i / PROJW, n = i - k * PROJW;
        wcat[i] = (n < 256) ? Woff[k * 256 + n] : Wattn[k * 128 + n - 256];
    }
    if (i < PROJW) bcat[i] = (i < 256) ? boff[i] : battn[i - 256];
}

// ---------------------------------------------------------------------------
// Tensor-core FP16 GEMM (fp32 accum): Cout = A(MxK=256)*W(256xN)+bias(+resid)
//   A_ILV: A row m at A[(s*Bc+b)*256+k] (m = b*Lseq+s). OUT_MODE 1: residual,
//   interleaved output. OUT_HALF: write __half output (g_val).
// BM=128, BN=128, BK=32. 8 warps (2x4), warp tile 64x32, m16n8k16.
// Smem: A fp16 [m][40] (ldmatrix conflict-free); B k-pair-packed half2
// Bp[kp][136] (staging STS.128 + frag LDS conflict-free). Double-buffered.
// ---------------------------------------------------------------------------
template<bool A_ILV, int OUT_MODE, bool OUT_HALF>
__global__ __launch_bounds__(256)
void hgemm_tc(const float* __restrict__ A, const float* __restrict__ W,
              const float* __restrict__ bias, void* __restrict__ Cout,
              int M, int Lseq, int ldw, int ldc,
              const float* __restrict__ resid)
{
    __shared__ __half    As[2][128][40];    // [stage][m][k-half], 80B rows
    __shared__ uint32_t  Bp[2][16][136];    // [stage][kpair][n] packed half2

    const int tid  = threadIdx.x;
    const int warp = tid >> 5;
    const int lane = tid & 31;
    const int wm = warp >> 2;          // 0..1
    const int wn = warp & 3;           // 0..3
    const int m0 = blockIdx.x * 128;
    const int n0 = blockIdx.y * 128;
    const int qr = lane >> 2;          // 0..7
    const int qc = lane & 3;           // 0..3

    // ---- staging slots ----
    // A: 512 dual-float4 slots (128 rows x 4), 2 per thread
    int arow[2], ac8[2];
    const float* aptr[2];
    #pragma unroll
    for (int r = 0; r < 2; r++) {
        int idx = tid + r * 256;
        arow[r] = idx >> 2;            // 0..127
        ac8[r]  = (idx & 3) * 8;       // 0,8,16,24 (float col)
        int m = m0 + arow[r];
        if (m < M) {
            int off;
            if (A_ILV) { int b = m / Lseq; int s = m - b * Lseq;
                         off = (s * Bc + b) * Cc; }
            else       { off = m * Cc; }
            aptr[r] = A + off;
        } else aptr[r] = nullptr;
    }
    // W: 512 slots (16 kpairs x 32 n-quads), 2 per thread
    int wkp[2], wn4[2];
    #pragma unroll
    for (int r = 0; r < 2; r++) {
        int idx = tid + r * 256;
        wkp[r] = idx >> 5;             // 0..15
        wn4[r] = (idx & 31) * 4;       // 0..124
    }
    const float* wbase = W + n0;

    float acc[4][4][4];
    #pragma unroll
    for (int mt = 0; mt < 4; mt++)
        #pragma unroll
        for (int nt = 0; nt < 4; nt++)
            #pragma unroll
            for (int c = 0; c < 4; c++) acc[mt][nt][c] = 0.f;

    const float4 f4z = make_float4(0.f, 0.f, 0.f, 0.f);

    float4 na[2][2], nw[2][2];
    auto load_tile = [&](int kb) {
        #pragma unroll
        for (int r = 0; r < 2; r++) {
            if (aptr[r]) {
                na[r][0] = *(const float4*)(aptr[r] + kb + ac8[r]);
                na[r][1] = *(const float4*)(aptr[r] + kb + ac8[r] + 4);
            } else { na[r][0] = f4z; na[r][1] = f4z; }
            nw[r][0] = *(const float4*)(wbase + (kb + 2 * wkp[r]    ) * ldw + wn4[r]);
            nw[r][1] = *(const float4*)(wbase + (kb + 2 * wkp[r] + 1) * ldw + wn4[r]);
        }
    };
    auto store_tile = [&](int st) {
        #pragma unroll
        for (int r = 0; r < 2; r++) {
            uint4 a4;
            a4.x = pack_h2(na[r][0].x, na[r][0].y);
            a4.y = pack_h2(na[r][0].z, na[r][0].w);
            a4.z = pack_h2(na[r][1].x, na[r][1].y);
            a4.w = pack_h2(na[r][1].z, na[r][1].w);
            *(uint4*)&As[st][arow[r]][ac8[r]] = a4;
            uint4 w4;
            w4.x = pack_h2(nw[r][0].x, nw[r][1].x);
            w4.y = pack_h2(nw[r][0].y, nw[r][1].y);
            w4.z = pack_h2(nw[r][0].z, nw[r][1].z);
            w4.w = pack_h2(nw[r][0].w, nw[r][1].w);
            *(uint4*)&Bp[st][wkp[r]][wn4[r]] = w4;
        }
    };

    // prologue
    load_tile(0);
    store_tile(0);
    __syncthreads();

    #pragma unroll 1
    for (int kk = 0; kk < Cc / 32; kk++) {
        const int cur = kk & 1;
        if (kk < Cc / 32 - 1) load_tile((kk + 1) * 32);

        #pragma unroll
        for (int ks = 0; ks < 32; ks += 16) {
            // A fragments via ldmatrix.x4
            uint32_t afr[4][4];
            #pragma unroll
            for (int mt = 0; mt < 4; mt++) {
                int rowb = wm * 64 + mt * 16;
                int row = rowb + (lane & 7) + ((lane >> 3) & 1) * 8;
                int col = ks + (lane >> 4) * 8;
                uint32_t sa = (uint32_t)__cvta_generic_to_shared(&As[cur][row][col]);
                ldmatrix_x4(afr[mt], sa);
            }
            // B fragments: conflict-free scalar LDS
            uint32_t bfr[4][2];
            #pragma unroll
            for (int nt = 0; nt < 4; nt++) {
                int col = wn * 32 + nt * 8 + qr;
                bfr[nt][0] = Bp[cur][ks / 2 + qc    ][col];
                bfr[nt][1] = Bp[cur][ks / 2 + qc + 4][col];
            }
            #pragma unroll
            for (int mt = 0; mt < 4; mt++)
                #pragma unroll
                for (int nt = 0; nt < 4; nt++)
                    mma_f16(acc[mt][nt], afr[mt], bfr[nt][0], bfr[nt][1]);
        }

        if (kk < Cc / 32 - 1) {
            store_tile(cur ^ 1);
            __syncthreads();
        }
    }

    // ---- epilogue ----
    float2 bvals[4];
    #pragma unroll
    for (int nt = 0; nt < 4; nt++) {
        int n = n0 + wn * 32 + nt * 8 + qc * 2;
        bvals[nt] = *(const float2*)&bias[n];
    }

    #pragma unroll
    for (int mt = 0; mt < 4; mt++) {
        #pragma unroll
        for (int hrow = 0; hrow < 2; hrow++) {
            int m = m0 + wm * 64 + mt * 16 + qr + hrow * 8;
            if (m >= M) continue;
            int obase;
            if (OUT_MODE == 1) {
                int b = m / Lseq; int s = m - b * Lseq;
                obase = (s * Bc + b) * Cc;
            } else {
                obase = m * ldc;
            }
            #pragma unroll
            for (int nt = 0; nt < 4; nt++) {
                int n = n0 + wn * 32 + nt * 8 + qc * 2;
                float vx = acc[mt][nt][hrow * 2 + 0] + bvals[nt].x;
                float vy = acc[mt][nt][hrow * 2 + 1] + bvals[nt].y;
                if (OUT_MODE == 1) {
                    float2 rr = *(const float2*)&resid[obase + n];
                    vx += rr.x; vy += rr.y;
                }
                if (OUT_HALF) {
                    __half2* op = (__half2*)((__half*)Cout + obase + n);
                    *op = __floats2half2_rn(vx, vy);
                } else {
                    *(float2*)((float*)Cout + obase + n) = make_float2(vx, vy);
                }
            }
        }
    }
}

// ---------------------------------------------------------------------------
// Fused softmax + bilinear sampling — fp16 value gathers (LDG.64).
// One warp per (b,q,head). Block 512 = 16 warps = 2 queries.
// ---------------------------------------------------------------------------
__device__ __forceinline__ float4 ldval_h(const uint2* p) {
    uint2 u = *p;
    __half2 h0 = *reinterpret_cast<__half2*>(&u.x);
    __half2 h1 = *reinterpret_cast<__half2*>(&u.y);
    float2 f0 = __half22float2(h0);
    float2 f1 = __half22float2(h1);
    return make_float4(f0.x, f0.y, f1.x, f1.y);
}

__global__ __launch_bounds__(512)
void msda_sample(const float* __restrict__ rp,
                 const __half* __restrict__ val,
                 const float* __restrict__ proj,
                 float* __restrict__ msda)
{
    const int gw   = (blockIdx.x * 512 + threadIdx.x) >> 5;
    const int lane = threadIdx.x & 31;
    const int bq   = gw >> 3;
    const int h    = gw & 7;
    const int g    = lane >> 3;
    const int cq   = lane & 7;
    const int b    = bq / LQc;

    const float* prow = proj + bq * PROJW;
    float off = prow[h * 32 + lane];
    float lg  = (lane < 16) ? prow[256 + h * 16 + lane] : -1e30f;
    float rpv = (lane < 8)  ? rp[bq * (Lc * 2) + lane] : 0.f;

    float mx = lg;
    #pragma unroll
    for (int o = 8; o > 0; o >>= 1)
        mx = fmaxf(mx, __shfl_xor_sync(0xffffffffu, mx, o));
    float e = (lane < 16) ? __expf(lg - mx) : 0.f;
    float sum = e;
    #pragma unroll
    for (int o = 8; o > 0; o >>= 1)
        sum += __shfl_xor_sync(0xffffffffu, sum, o);
    float attn_val = e / sum;

    constexpr int HH[4] = {100, 50, 25, 13};
    constexpr int ST[4] = {0, 10000, 12500, 13125};

    // uint2 units: 256 halves/pixel = 64 uint2; lane covers 4 channels
    const uint2* vb = (const uint2*)val + (b * LVc) * 64 + h * 8 + cq;

    float4 acc = make_float4(0.f, 0.f, 0.f, 0.f);

    #pragma unroll
    for (int l = 0; l < Lc; l++) {
        const int   Wl = HH[l];
        const int   st = ST[l];
        const float fW = (float)HH[l];

        float rpx = __shfl_sync(0xffffffffu, rpv, 2 * l);
        float rpy = __shfl_sync(0xffffffffu, rpv, 2 * l + 1);
        rpx = fminf(fmaxf(rpx, 1e-5f), 1.f - 1e-5f);
        rpy = fminf(fmaxf(rpy, 1e-5f), 1.f - 1e-5f);

        float offx = __shfl_sync(0xffffffffu, off, l * 8 + 2 * g);
        float offy = __shfl_sync(0xffffffffu, off, l * 8 + 2 * g + 1);

        float x = fmaf(rpx, fW, offx) - 0.5f;
        float y = fmaf(rpy, fW, offy) - 0.5f;
        float x0f = floorf(x), y0f = floorf(y);
        int x0 = (int)x0f, y0 = (int)y0f;
        float wx = x - x0f, wy = y - y0f;

        float a = __shfl_sync(0xffffffffu, attn_val, l * 4 + g);

        float w00 = a * (1.f - wy) * (1.f - wx);
        float w01 = a * (1.f - wy) * wx;
        float w10 = a * wy * (1.f - wx);
        float w11 = a * wy * wx;

        int x1 = x0 + 1, y1 = y0 + 1;
        bool vx0 = (x0 >= 0) & (x0 < Wl);
        bool vx1 = (x1 >= 0) & (x1 < Wl);
        bool vy0 = (y0 >= 0) & (y0 < Wl);
        bool vy1 = (y1 >= 0) & (y1 < Wl);

        int row0 = (st + y0 * Wl) * 64;
        int row1 = row0 + Wl * 64;

        if (vy0 & vx0) {
            float4 v = ldval_h(vb + row0 + x0 * 64);
            acc.x = fmaf(w00, v.x, acc.x); acc.y = fmaf(w00, v.y, acc.y);
            acc.z = fmaf(w00, v.z, acc.z); acc.w = fmaf(w00, v.w, acc.w);
        }
        if (vy0 & vx1) {
            float4 v = ldval_h(vb + row0 + x1 * 64);
            acc.x = fmaf(w01, v.x, acc.x); acc.y = fmaf(w01, v.y, acc.y);
            acc.z = fmaf(w01, v.z, acc.z); acc.w = fmaf(w01, v.w, acc.w);
        }
        if (vy1 & vx0) {
            float4 v = ldval_h(vb + row1 + x0 * 64);
            acc.x = fmaf(w10, v.x, acc.x); acc.y = fmaf(w10, v.y, acc.y);
            acc.z = fmaf(w10, v.z, acc.z); acc.w = fmaf(w10, v.w, acc.w);
        }
        if (vy1 & vx1) {
            float4 v = ldval_h(vb + row1 + x1 * 64);
            acc.x = fmaf(w11, v.x, acc.x); acc.y = fmaf(w11, v.y, acc.y);
            acc.z = fmaf(w11, v.z, acc.z); acc.w = fmaf(w11, v.w, acc.w);
        }
    }

    #pragma unroll
    for (int o = 8; o <= 16; o <<= 1) {
        acc.x += __shfl_xor_sync(0xffffffffu, acc.x, o);
        acc.y += __shfl_xor_sync(0xffffffffu, acc.y, o);
        acc.z += __shfl_xor_sync(0xffffffffu, acc.z, o);
        acc.w += __shfl_xor_sync(0xffffffffu, acc.w, o);
    }

    if (g == 0) {
        ((float4*)msda)[bq * (Cc / 4) + h * 8 + cq] = acc;
    }
}

// ---------------------------------------------------------------------------
extern "C" void kernel_launch(void* const* d_in, const int* in_sizes, int n_in,
                              void* d_out, int out_size)
{
    const float* query = (const float*)d_in[0];   // (LQ, B, C)
    const float* rp    = (const float*)d_in[1];   // (B, LQ, L, 2)
    const float* value = (const float*)d_in[2];   // (LV, B, C)
    const float* Wv    = (const float*)d_in[5];
    const float* bv    = (const float*)d_in[6];
    const float* Woff  = (const float*)d_in[7];
    const float* boff  = (const float*)d_in[8];
    const float* Wattn = (const float*)d_in[9];
    const float* battn = (const float*)d_in[10];
    const float* Wo    = (const float*)d_in[11];
    const float* bo    = (const float*)d_in[12];
    float* out = (float*)d_out;

    __half* valp;
    float *projp, *msdap, *wcatp, *bcatp;
    cudaGetSymbolAddress((void**)&valp,  g_val);
    cudaGetSymbolAddress((void**)&projp, g_proj);
    cudaGetSymbolAddress((void**)&msdap, g_msda);
    cudaGetSymbolAddress((void**)&wcatp, g_wcat);
    cudaGetSymbolAddress((void**)&bcatp, g_bcat);

    const int gm = (Mrows + 127) / 128;   // 208

    // 0) concat Woff||Wattn, boff||battn
    concat_w<<<(Cc * PROJW + 255) / 256, 256>>>(Woff, boff, Wattn, battn,
                                                wcatp, bcatp);
    // 1) value projection -> fp16 g_val
    hgemm_tc<true, 0, true><<<dim3(gm, 2), 256>>>(value, Wv, bv, valp,
                                                  Mrows, LVc, 256, 256, nullptr);
    // 2) fused offset+attn projection -> g_proj
    hgemm_tc<true, 0, false><<<dim3(gm, 3), 256>>>(query, wcatp, bcatp, projp,
                                                   Mrows, LQc, PROJW, PROJW, nullptr);
    // 3) softmax + bilinear sampling -> g_msda
    msda_sample<<<Mrows / 2, 512>>>(rp, valp, projp, msdap);
    // 4) output projection + bias + residual -> d_out
    hgemm_tc<false, 1, false><<<dim3(gm, 2), 256>>>(msdap, Wo, bo, out,
                                                    Mrows, LQc, 256, 256, query);
}

// round 7
// speedup vs baseline: 2.6015x; 1.0908x over previous
#include <cuda_runtime.h>
#include <cuda_fp16.h>
#include <math.h>
#include <stdint.h>

// ---------------------------------------------------------------------------
// Problem constants (fixed instance)
// ---------------------------------------------------------------------------
constexpr int Bc  = 2;
constexpr int Cc  = 256;
constexpr int NHc = 8;
constexpr int Lc  = 4;
constexpr int Pc  = 4;
constexpr int LVc = 13294;       // 100*100 + 50*50 + 25*25 + 13*13
constexpr int LQc = 13294;
constexpr int Mrows = Bc * LQc;  // 26588
constexpr int PROJW = NHc * Lc * Pc * 2 + NHc * Lc * Pc; // 384

// Scratch (device globals; no allocation allowed)
__device__ __half g_val [Bc * LVc * Cc];    // [b][lv][c]  fp16
__device__ float  g_proj[Bc * LQc * PROJW]; // [b][q][384]
__device__ __half g_msda[Bc * LQc * Cc];    // [b][q][c]   fp16
__device__ float  g_wcat[Cc * PROJW];       // Woff || Wattn
__device__ float  g_bcat[PROJW];            // boff || battn

// ---------------------------------------------------------------------------
// fp16 MMA helpers
// ---------------------------------------------------------------------------
__device__ __forceinline__ uint32_t pack_h2(float a, float b) {
    __half2 h = __floats2half2_rn(a, b);
    return *reinterpret_cast<uint32_t*>(&h);
}
__device__ __forceinline__ void ldmatrix_x4(uint32_t (&r)[4], uint32_t saddr) {
    asm volatile("ldmatrix.sync.aligned.m8n8.x4.shared.b16 {%0,%1,%2,%3}, [%4];"
                 : "=r"(r[0]), "=r"(r[1]), "=r"(r[2]), "=r"(r[3])
                 : "r"(saddr));
}
__device__ __forceinline__ void mma_f16(float (&d)[4],
                                        const uint32_t (&a)[4],
                                        const uint32_t b0, const uint32_t b1) {
    asm volatile(
        "mma.sync.aligned.m16n8k16.row.col.f32.f16.f16.f32 "
        "{%0,%1,%2,%3}, {%4,%5,%6,%7}, {%8,%9}, {%0,%1,%2,%3};"
        : "+f"(d[0]), "+f"(d[1]), "+f"(d[2]), "+f"(d[3])
        : "r"(a[0]), "r"(a[1]), "r"(a[2]), "r"(a[3]), "r"(b0), "r"(b1));
}

// ---------------------------------------------------------------------------
// Weight/bias concat: g_wcat[k][n] = n<256 ? Woff[k][n] : Wattn[k][n-256]
// ---------------------------------------------------------------------------
__global__ void concat_w(const float* __restrict__ Woff,
                         const float* __restrict__ boff,
                         const float* __restrict__ Wattn,
                         const float* __restrict__ battn,
                         float* __restrict__ wcat, float* __restrict__ bcat)
{
    int i = blockIdx.x * 256 + threadIdx.x;
    if (i < Cc * PROJW) {
        int k = i / PROJW, n = i - k * PROJW;
        wcat[i] = (n < 256) ? Woff[k * 256 + n] : Wattn[k * 128 + n - 256];
    }
    if (i < PROJW) bcat[i] = (i < 256) ? boff[i] : battn[i - 256];
}

// ---------------------------------------------------------------------------
// Tensor-core FP16 GEMM (fp32 accum): Cout = A(MxK=256)*W(256xN)+bias(+resid)
//   A_ILV: A row m at A[(s*Bc+b)*256+k]. OUT_MODE 1: residual + interleaved
//   output. OUT_HALF: __half output. A_HALF: A is __half (direct copy staging).
// BM=128, BN=128, BK=32. 8 warps (2x4), warp tile 64x32, m16n8k16.
// ---------------------------------------------------------------------------
template<bool A_ILV, int OUT_MODE, bool OUT_HALF, bool A_HALF>
__global__ __launch_bounds__(256)
void hgemm_tc(const void* __restrict__ Ain, const float* __restrict__ W,
              const float* __restrict__ bias, void* __restrict__ Cout,
              int M, int Lseq, int ldw, int ldc,
              const float* __restrict__ resid)
{
    __shared__ __half    As[2][128][40];    // [stage][m][k-half]
    __shared__ uint32_t  Bp[2][16][136];    // [stage][kpair][n] packed half2

    const int tid  = threadIdx.x;
    const int warp = tid >> 5;
    const int lane = tid & 31;
    const int wm = warp >> 2;          // 0..1
    const int wn = warp & 3;           // 0..3
    const int m0 = blockIdx.x * 128;
    const int n0 = blockIdx.y * 128;
    const int qr = lane >> 2;          // 0..7
    const int qc = lane & 3;           // 0..3

    // ---- staging slots ----
    int arow[2], ac8[2];
    const void* aptr[2];
    #pragma unroll
    for (int r = 0; r < 2; r++) {
        int idx = tid + r * 256;
        arow[r] = idx >> 2;            // 0..127
        ac8[r]  = (idx & 3) * 8;       // element offset in k-tile
        int m = m0 + arow[r];
        if (m < M) {
            int off;
            if (A_ILV) { int b = m / Lseq; int s = m - b * Lseq;
                         off = (s * Bc + b) * Cc; }
            else       { off = m * Cc; }
            if (A_HALF) aptr[r] = (const __half*)Ain + off;
            else        aptr[r] = (const float*)Ain + off;
        } else aptr[r] = nullptr;
    }
    int wkp[2], wn4[2];
    #pragma unroll
    for (int r = 0; r < 2; r++) {
        int idx = tid + r * 256;
        wkp[r] = idx >> 5;             // 0..15
        wn4[r] = (idx & 31) * 4;       // 0..124
    }
    const float* wbase = W + n0;

    float acc[4][4][4];
    #pragma unroll
    for (int mt = 0; mt < 4; mt++)
        #pragma unroll
        for (int nt = 0; nt < 4; nt++)
            #pragma unroll
            for (int c = 0; c < 4; c++) acc[mt][nt][c] = 0.f;

    const float4 f4z = make_float4(0.f, 0.f, 0.f, 0.f);

    float4 na[2][2], nw[2][2];
    uint4 ua[2];
    auto load_tile = [&](int kb) {
        #pragma unroll
        for (int r = 0; r < 2; r++) {
            if (A_HALF) {
                if (aptr[r]) ua[r] = *(const uint4*)((const __half*)aptr[r] + kb + ac8[r]);
                else         ua[r] = make_uint4(0, 0, 0, 0);
            } else {
                if (aptr[r]) {
                    na[r][0] = *(const float4*)((const float*)aptr[r] + kb + ac8[r]);
                    na[r][1] = *(const float4*)((const float*)aptr[r] + kb + ac8[r] + 4);
                } else { na[r][0] = f4z; na[r][1] = f4z; }
            }
            nw[r][0] = *(const float4*)(wbase + (kb + 2 * wkp[r]    ) * ldw + wn4[r]);
            nw[r][1] = *(const float4*)(wbase + (kb + 2 * wkp[r] + 1) * ldw + wn4[r]);
        }
    };
    auto store_tile = [&](int st) {
        #pragma unroll
        for (int r = 0; r < 2; r++) {
            if (A_HALF) {
                *(uint4*)&As[st][arow[r]][ac8[r]] = ua[r];
            } else {
                uint4 a4;
                a4.x = pack_h2(na[r][0].x, na[r][0].y);
                a4.y = pack_h2(na[r][0].z, na[r][0].w);
                a4.z = pack_h2(na[r][1].x, na[r][1].y);
                a4.w = pack_h2(na[r][1].z, na[r][1].w);
                *(uint4*)&As[st][arow[r]][ac8[r]] = a4;
            }
            uint4 w4;
            w4.x = pack_h2(nw[r][0].x, nw[r][1].x);
            w4.y = pack_h2(nw[r][0].y, nw[r][1].y);
            w4.z = pack_h2(nw[r][0].z, nw[r][1].z);
            w4.w = pack_h2(nw[r][0].w, nw[r][1].w);
            *(uint4*)&Bp[st][wkp[r]][wn4[r]] = w4;
        }
    };

    load_tile(0);
    store_tile(0);
    __syncthreads();

    #pragma unroll 1
    for (int kk = 0; kk < Cc / 32; kk++) {
        const int cur = kk & 1;
        if (kk < Cc / 32 - 1) load_tile((kk + 1) * 32);

        #pragma unroll
        for (int ks = 0; ks < 32; ks += 16) {
            uint32_t afr[4][4];
            #pragma unroll
            for (int mt = 0; mt < 4; mt++) {
                int rowb = wm * 64 + mt * 16;
                int row = rowb + (lane & 7) + ((lane >> 3) & 1) * 8;
                int col = ks + (lane >> 4) * 8;
                uint32_t sa = (uint32_t)__cvta_generic_to_shared(&As[cur][row][col]);
                ldmatrix_x4(afr[mt], sa);
            }
            uint32_t bfr[4][2];
            #pragma unroll
            for (int nt = 0; nt < 4; nt++) {
                int col = wn * 32 + nt * 8 + qr;
                bfr[nt][0] = Bp[cur][ks / 2 + qc    ][col];
                bfr[nt][1] = Bp[cur][ks / 2 + qc + 4][col];
            }
            #pragma unroll
            for (int mt = 0; mt < 4; mt++)
                #pragma unroll
                for (int nt = 0; nt < 4; nt++)
                    mma_f16(acc[mt][nt], afr[mt], bfr[nt][0], bfr[nt][1]);
        }

        if (kk < Cc / 32 - 1) {
            store_tile(cur ^ 1);
            __syncthreads();
        }
    }

    // ---- epilogue ----
    float2 bvals[4];
    #pragma unroll
    for (int nt = 0; nt < 4; nt++) {
        int n = n0 + wn * 32 + nt * 8 + qc * 2;
        bvals[nt] = *(const float2*)&bias[n];
    }

    #pragma unroll
    for (int mt = 0; mt < 4; mt++) {
        #pragma unroll
        for (int hrow = 0; hrow < 2; hrow++) {
            int m = m0 + wm * 64 + mt * 16 + qr + hrow * 8;
            if (m >= M) continue;
            int obase;
            if (OUT_MODE == 1) {
                int b = m / Lseq; int s = m - b * Lseq;
                obase = (s * Bc + b) * Cc;
            } else {
                obase = m * ldc;
            }
            #pragma unroll
            for (int nt = 0; nt < 4; nt++) {
                int n = n0 + wn * 32 + nt * 8 + qc * 2;
                float vx = acc[mt][nt][hrow * 2 + 0] + bvals[nt].x;
                float vy = acc[mt][nt][hrow * 2 + 1] + bvals[nt].y;
                if (OUT_MODE == 1) {
                    float2 rr = *(const float2*)&resid[obase + n];
                    vx += rr.x; vy += rr.y;
                }
                if (OUT_HALF) {
                    __half2* op = (__half2*)((__half*)Cout + obase + n);
                    *op = __floats2half2_rn(vx, vy);
                } else {
                    *(float2*)((float*)Cout + obase + n) = make_float2(vx, vy);
                }
            }
        }
    }
}

// ---------------------------------------------------------------------------
// Fused softmax + bilinear sampling — 2 queries per warp (16-lane halves).
// Warp gw: pair = gw>>3, head = gw&7; lane half = query (bq = 2*pair+half).
// Within half: g2 = hl>>3 (point group), cq = hl&7 (channel quad).
// Points per level processed in 2 sub-iterations (p = 2*pp + g2).
// All scalar math serves two queries at once; width-16 shuffles.
// ---------------------------------------------------------------------------
__device__ __forceinline__ float4 ldval_h(const uint2* p) {
    uint2 u = *p;
    __half2 h0 = *reinterpret_cast<__half2*>(&u.x);
    __half2 h1 = *reinterpret_cast<__half2*>(&u.y);
    float2 f0 = __half22float2(h0);
    float2 f1 = __half22float2(h1);
    return make_float4(f0.x, f0.y, f1.x, f1.y);
}
#define SHFL16(v, s) __shfl_sync(0xffffffffu, (v), (s), 16)

__global__ __launch_bounds__(512)
void msda_sample(const float* __restrict__ rp,
                 const __half* __restrict__ val,
                 const float* __restrict__ proj,
                 __half* __restrict__ msda)
{
    const int gw   = (blockIdx.x * 512 + threadIdx.x) >> 5;
    const int lane = threadIdx.x & 31;
    const int pair = gw >> 3;
    const int h    = gw & 7;
    const int hl   = lane & 15;            // lane within query-half
    const int bq   = pair * 2 + (lane >> 4);
    const int g2   = hl >> 3;              // 0..1 point group
    const int cq   = hl & 7;               // channel quad
    const int b    = bq / LQc;

    const float* prow = proj + bq * PROJW;
    float off0 = prow[h * 32 + hl];        // offsets 0..15
    float off1 = prow[h * 32 + 16 + hl];   // offsets 16..31
    float lg   = prow[256 + h * 16 + hl];  // all 16 logits
    float rpv  = 0.f;
    if (hl < 8) {
        rpv = rp[bq * (Lc * 2) + hl];
        rpv = fminf(fmaxf(rpv, 1e-5f), 1.f - 1e-5f);
    }

    // Softmax over 16 logits (xor offsets 1..8 stay within each 16-lane half)
    float mx = lg;
    #pragma unroll
    for (int o = 8; o > 0; o >>= 1)
        mx = fmaxf(mx, __shfl_xor_sync(0xffffffffu, mx, o));
    float e = __expf(lg - mx);
    float sum = e;
    #pragma unroll
    for (int o = 8; o > 0; o >>= 1)
        sum += __shfl_xor_sync(0xffffffffu, sum, o);
    float attn_val = e / sum;

    constexpr int HH[4] = {100, 50, 25, 13};
    constexpr int ST[4] = {0, 10000, 12500, 13125};

    // uint2 units: 256 halves/pixel = 64 uint2; lane covers 4 channels
    const uint2* vb = (const uint2*)val + (b * LVc) * 64 + h * 8 + cq;

    float4 acc = make_float4(0.f, 0.f, 0.f, 0.f);

    #pragma unroll
    for (int l = 0; l < Lc; l++) {
        const int   Wl = HH[l];
        const int   st = ST[l];
        const float fW = (float)HH[l];

        float rpx = SHFL16(rpv, 2 * l);
        float rpy = SHFL16(rpv, 2 * l + 1);

        #pragma unroll
        for (int pp = 0; pp < 2; pp++) {
            const int p = pp * 2 + g2;                 // point 0..3 (lane-dep)
            const int oidx = l * 8 + 2 * p;            // offset pair index 0..30
            float offx, offy;
            if (l < 2) { offx = SHFL16(off0, oidx);      offy = SHFL16(off0, oidx + 1); }
            else       { offx = SHFL16(off1, oidx - 16); offy = SHFL16(off1, oidx - 15); }
            float a = SHFL16(attn_val, l * 4 + p);

            float x = fmaf(rpx, fW, offx) - 0.5f;
            float y = fmaf(rpy, fW, offy) - 0.5f;
            float x0f = floorf(x), y0f = floorf(y);
            int x0 = (int)x0f, y0 = (int)y0f;
            float wx = x - x0f, wy = y - y0f;

            float w00 = a * (1.f - wy) * (1.f - wx);
            float w01 = a * (1.f - wy) * wx;
            float w10 = a * wy * (1.f - wx);
            float w11 = a * wy * wx;

            int x1 = x0 + 1, y1 = y0 + 1;
            bool vx0 = (x0 >= 0) & (x0 < Wl);
            bool vx1 = (x1 >= 0) & (x1 < Wl);
            bool vy0 = (y0 >= 0) & (y0 < Wl);
            bool vy1 = (y1 >= 0) & (y1 < Wl);

            int row0 = (st + y0 * Wl) * 64;
            int row1 = row0 + Wl * 64;

            if (vy0 & vx0) {
                float4 v = ldval_h(vb + row0 + x0 * 64);
                acc.x = fmaf(w00, v.x, acc.x); acc.y = fmaf(w00, v.y, acc.y);
                acc.z = fmaf(w00, v.z, acc.z); acc.w = fmaf(w00, v.w, acc.w);
            }
            if (vy0 & vx1) {
                float4 v = ldval_h(vb + row0 + x1 * 64);
                acc.x = fmaf(w01, v.x, acc.x); acc.y = fmaf(w01, v.y, acc.y);
                acc.z = fmaf(w01, v.z, acc.z); acc.w = fmaf(w01, v.w, acc.w);
            }
            if (vy1 & vx0) {
                float4 v = ldval_h(vb + row1 + x0 * 64);
                acc.x = fmaf(w10, v.x, acc.x); acc.y = fmaf(w10, v.y, acc.y);
                acc.z = fmaf(w10, v.z, acc.z); acc.w = fmaf(w10, v.w, acc.w);
            }
            if (vy1 & vx1) {
                float4 v = ldval_h(vb + row1 + x1 * 64);
                acc.x = fmaf(w11, v.x, acc.x); acc.y = fmaf(w11, v.y, acc.y);
                acc.z = fmaf(w11, v.z, acc.z); acc.w = fmaf(w11, v.w, acc.w);
            }
        }
    }

    // Reduce across the 2 point-groups (xor 8: stays within 16-lane half)
    acc.x += __shfl_xor_sync(0xffffffffu, acc.x, 8);
    acc.y += __shfl_xor_sync(0xffffffffu, acc.y, 8);
    acc.z += __shfl_xor_sync(0xffffffffu, acc.z, 8);
    acc.w += __shfl_xor_sync(0xffffffffu, acc.w, 8);

    if (g2 == 0) {
        uint2 o;
        o.x = pack_h2(acc.x, acc.y);
        o.y = pack_h2(acc.z, acc.w);
        ((uint2*)msda)[bq * 64 + h * 8 + cq] = o;
    }
}

// ---------------------------------------------------------------------------
extern "C" void kernel_launch(void* const* d_in, const int* in_sizes, int n_in,
                              void* d_out, int out_size)
{
    const float* query = (const float*)d_in[0];   // (LQ, B, C)
    const float* rp    = (const float*)d_in[1];   // (B, LQ, L, 2)
    const float* value = (const float*)d_in[2];   // (LV, B, C)
    const float* Wv    = (const float*)d_in[5];
    const float* bv    = (const float*)d_in[6];
    const float* Woff  = (const float*)d_in[7];
    const float* boff  = (const float*)d_in[8];
    const float* Wattn = (const float*)d_in[9];
    const float* battn = (const float*)d_in[10];
    const float* Wo    = (const float*)d_in[11];
    const float* bo    = (const float*)d_in[12];
    float* out = (float*)d_out;

    __half *valp, *msdap;
    float *projp, *wcatp, *bcatp;
    cudaGetSymbolAddress((void**)&valp,  g_val);
    cudaGetSymbolAddress((void**)&projp, g_proj);
    cudaGetSymbolAddress((void**)&msdap, g_msda);
    cudaGetSymbolAddress((void**)&wcatp, g_wcat);
    cudaGetSymbolAddress((void**)&bcatp, g_bcat);

    const int gm = (Mrows + 127) / 128;   // 208

    // 0) concat Woff||Wattn, boff||battn
    concat_w<<<(Cc * PROJW + 255) / 256, 256>>>(Woff, boff, Wattn, battn,
                                                wcatp, bcatp);
    // 1) value projection -> fp16 g_val
    hgemm_tc<true, 0, true, false><<<dim3(gm, 2), 256>>>(
        value, Wv, bv, valp, Mrows, LVc, 256, 256, nullptr);
    // 2) fused offset+attn projection -> g_proj
    hgemm_tc<true, 0, false, false><<<dim3(gm, 3), 256>>>(
        query, wcatp, bcatp, projp, Mrows, LQc, PROJW, PROJW, nullptr);
    // 3) softmax + bilinear sampling -> fp16 g_msda (2 queries per warp)
    msda_sample<<<(Mrows / 2 * NHc) / 16, 512>>>(rp, valp, projp, msdap);
    // 4) output projection + bias + residual -> d_out (A in fp16)
    hgemm_tc<false, 1, false, true><<<dim3(gm, 2), 256>>>(
        msdap, Wo, bo, out, Mrows, LQc, 256, 256, query);
}

// round 9
// speedup vs baseline: 2.7972x; 1.0752x over previous
#include <cuda_runtime.h>
#include <cuda_fp16.h>
#include <math.h>
#include <stdint.h>

// ---------------------------------------------------------------------------
// Problem constants (fixed instance)
// ---------------------------------------------------------------------------
constexpr int Bc  = 2;
constexpr int Cc  = 256;
constexpr int NHc = 8;
constexpr int Lc  = 4;
constexpr int Pc  = 4;
constexpr int LVc = 13294;       // 100*100 + 50*50 + 25*25 + 13*13
constexpr int LQc = 13294;
constexpr int Mrows = Bc * LQc;  // 26588
constexpr int PROJW = NHc * Lc * Pc * 2 + NHc * Lc * Pc; // 384

// Scratch (device globals; no allocation allowed)
__device__ __half g_val [Bc * LVc * Cc];    // [b][lv][c]  fp16
__device__ __half g_proj[Bc * LQc * PROJW]; // [b][q][384] fp16
__device__ __half g_msda[Bc * LQc * Cc];    // [b][q][c]   fp16
__device__ float  g_wcat[Cc * PROJW];       // Woff || Wattn
__device__ float  g_bcat[PROJW];            // boff || battn

// ---------------------------------------------------------------------------
// fp16 MMA helpers
// ---------------------------------------------------------------------------
__device__ __forceinline__ uint32_t pack_h2(float a, float b) {
    __half2 h = __floats2half2_rn(a, b);
    return *reinterpret_cast<uint32_t*>(&h);
}
__device__ __forceinline__ void ldmatrix_x4(uint32_t (&r)[4], uint32_t saddr) {
    asm volatile("ldmatrix.sync.aligned.m8n8.x4.shared.b16 {%0,%1,%2,%3}, [%4];"
                 : "=r"(r[0]), "=r"(r[1]), "=r"(r[2]), "=r"(r[3])
                 : "r"(saddr));
}
__device__ __forceinline__ void mma_f16(float (&d)[4],
                                        const uint32_t (&a)[4],
                                        const uint32_t b0, const uint32_t b1) {
    asm volatile(
        "mma.sync.aligned.m16n8k16.row.col.f32.f16.f16.f32 "
        "{%0,%1,%2,%3}, {%4,%5,%6,%7}, {%8,%9}, {%0,%1,%2,%3};"
        : "+f"(d[0]), "+f"(d[1]), "+f"(d[2]), "+f"(d[3])
        : "r"(a[0]), "r"(a[1]), "r"(a[2]), "r"(a[3]), "r"(b0), "r"(b1));
}

// ---------------------------------------------------------------------------
// Weight/bias concat: g_wcat[k][n] = n<256 ? Woff[k][n] : Wattn[k][n-256]
// ---------------------------------------------------------------------------
__global__ void concat_w(const float* __restrict__ Woff,
                         const float* __restrict__ boff,
                         const float* __restrict__ Wattn,
                         const float* __restrict__ battn,
                         float* __restrict__ wcat, float* __restrict__ bcat)
{
    int i = blockIdx.x * 256 + threadIdx.x;
    if (i < Cc * PROJW) {
        int k = i / PROJW, n = i - k * PROJW;
        wcat[i] = (n < 256) ? Woff[k * 256 + n] : Wattn[k * 128 + n - 256];
    }
    if (i < PROJW) bcat[i] = (i < 256) ? boff[i] : battn[i - 256];
}

// ---------------------------------------------------------------------------
// Tensor-core FP16 GEMM (fp32 accum): Cout = A(MxK=256)*W(256xN)+bias(+resid)
//   A_ILV: A row m at A[(s*Bc+b)*256+k]. OUT_MODE 1: residual + interleaved
//   output. OUT_HALF: __half output. A_HALF: A is __half (direct copy staging).
// BM=128, BN=128, BK=32. 8 warps (2x4), warp tile 64x32, m16n8k16.
// ---------------------------------------------------------------------------
template<bool A_ILV, int OUT_MODE, bool OUT_HALF, bool A_HALF>
__global__ __launch_bounds__(256)
void hgemm_tc(const void* __restrict__ Ain, const float* __restrict__ W,
              const float* __restrict__ bias, void* __restrict__ Cout,
              int M, int Lseq, int ldw, int ldc,
              const float* __restrict__ resid)
{
    __shared__ __half    As[2][128][40];    // [stage][m][k-half]
    __shared__ uint32_t  Bp[2][16][136];    // [stage][kpair][n] packed half2

    const int tid  = threadIdx.x;
    const int warp = tid >> 5;
    const int lane = tid & 31;
    const int wm = warp >> 2;          // 0..1
    const int wn = warp & 3;           // 0..3
    const int m0 = blockIdx.x * 128;
    const int n0 = blockIdx.y * 128;
    const int qr = lane >> 2;          // 0..7
    const int qc = lane & 3;           // 0..3

    // ---- staging slots ----
    int arow[2], ac8[2];
    const void* aptr[2];
    #pragma unroll
    for (int r = 0; r < 2; r++) {
        int idx = tid + r * 256;
        arow[r] = idx >> 2;            // 0..127
        ac8[r]  = (idx & 3) * 8;       // element offset in k-tile
        int m = m0 + arow[r];
        if (m < M) {
            int off;
            if (A_ILV) { int b = m / Lseq; int s = m - b * Lseq;
                         off = (s * Bc + b) * Cc; }
            else       { off = m * Cc; }
            if (A_HALF) aptr[r] = (const __half*)Ain + off;
            else        aptr[r] = (const float*)Ain + off;
        } else aptr[r] = nullptr;
    }
    int wkp[2], wn4[2];
    #pragma unroll
    for (int r = 0; r < 2; r++) {
        int idx = tid + r * 256;
        wkp[r] = idx >> 5;             // 0..15
        wn4[r] = (idx & 31) * 4;       // 0..124
    }
    const float* wbase = W + n0;

    float acc[4][4][4];
    #pragma unroll
    for (int mt = 0; mt < 4; mt++)
        #pragma unroll
        for (int nt = 0; nt < 4; nt++)
            #pragma unroll
            for (int c = 0; c < 4; c++) acc[mt][nt][c] = 0.f;

    const float4 f4z = make_float4(0.f, 0.f, 0.f, 0.f);

    float4 na[2][2], nw[2][2];
    uint4 ua[2];
    auto load_tile = [&](int kb) {
        #pragma unroll
        for (int r = 0; r < 2; r++) {
            if (A_HALF) {
                if (aptr[r]) ua[r] = *(const uint4*)((const __half*)aptr[r] + kb + ac8[r]);
                else         ua[r] = make_uint4(0, 0, 0, 0);
            } else {
                if (aptr[r]) {
                    na[r][0] = *(const float4*)((const float*)aptr[r] + kb + ac8[r]);
                    na[r][1] = *(const float4*)((const float*)aptr[r] + kb + ac8[r] + 4);
                } else { na[r][0] = f4z; na[r][1] = f4z; }
            }
            nw[r][0] = *(const float4*)(wbase + (kb + 2 * wkp[r]    ) * ldw + wn4[r]);
            nw[r][1] = *(const float4*)(wbase + (kb + 2 * wkp[r] + 1) * ldw + wn4[r]);
        }
    };
    auto store_tile = [&](int st) {
        #pragma unroll
        for (int r = 0; r < 2; r++) {
            if (A_HALF) {
                *(uint4*)&As[st][arow[r]][ac8[r]] = ua[r];
            } else {
                uint4 a4;
                a4.x = pack_h2(na[r][0].x, na[r][0].y);
                a4.y = pack_h2(na[r][0].z, na[r][0].w);
                a4.z = pack_h2(na[r][1].x, na[r][1].y);
                a4.w = pack_h2(na[r][1].z, na[r][1].w);
                *(uint4*)&As[st][arow[r]][ac8[r]] = a4;
            }
            uint4 w4;
            w4.x = pack_h2(nw[r][0].x, nw[r][1].x);
            w4.y = pack_h2(nw[r][0].y, nw[r][1].y);
            w4.z = pack_h2(nw[r][0].z, nw[r][1].z);
            w4.w = pack_h2(nw[r][0].w, nw[r][1].w);
            *(uint4*)&Bp[st][wkp[r]][wn4[r]] = w4;
        }
    };

    load_tile(0);
    store_tile(0);
    __syncthreads();

    #pragma unroll 1
    for (int kk = 0; kk < Cc / 32; kk++) {
        const int cur = kk & 1;
        if (kk < Cc / 32 - 1) load_tile((kk + 1) * 32);

        #pragma unroll
        for (int ks = 0; ks < 32; ks += 16) {
            uint32_t afr[4][4];
            #pragma unroll
            for (int mt = 0; mt < 4; mt++) {
                int rowb = wm * 64 + mt * 16;
                int row = rowb + (lane & 7) + ((lane >> 3) & 1) * 8;
                int col = ks + (lane >> 4) * 8;
                uint32_t sa = (uint32_t)__cvta_generic_to_shared(&As[cur][row][col]);
                ldmatrix_x4(afr[mt], sa);
            }
            uint32_t bfr[4][2];
            #pragma unroll
            for (int nt = 0; nt < 4; nt++) {
                int col = wn * 32 + nt * 8 + qr;
                bfr[nt][0] = Bp[cur][ks / 2 + qc    ][col];
                bfr[nt][1] = Bp[cur][ks / 2 + qc + 4][col];
            }
            #pragma unroll
            for (int mt = 0; mt < 4; mt++)
                #pragma unroll
                for (int nt = 0; nt < 4; nt++)
                    mma_f16(acc[mt][nt], afr[mt], bfr[nt][0], bfr[nt][1]);
        }

        if (kk < Cc / 32 - 1) {
            store_tile(cur ^ 1);
            __syncthreads();
        }
    }

    // ---- epilogue ----
    float2 bvals[4];
    #pragma unroll
    for (int nt = 0; nt < 4; nt++) {
        int n = n0 + wn * 32 + nt * 8 + qc * 2;
        bvals[nt] = *(const float2*)&bias[n];
    }

    #pragma unroll
    for (int mt = 0; mt < 4; mt++) {
        #pragma unroll
        for (int hrow = 0; hrow < 2; hrow++) {
            int m = m0 + wm * 64 + mt * 16 + qr + hrow * 8;
            if (m >= M) continue;
            int obase;
            if (OUT_MODE == 1) {
                int b = m / Lseq; int s = m - b * Lseq;
                obase = (s * Bc + b) * Cc;
            } else {
                obase = m * ldc;
            }
            #pragma unroll
            for (int nt = 0; nt < 4; nt++) {
                int n = n0 + wn * 32 + nt * 8 + qc * 2;
                float vx = acc[mt][nt][hrow * 2 + 0] + bvals[nt].x;
                float vy = acc[mt][nt][hrow * 2 + 1] + bvals[nt].y;
                if (OUT_MODE == 1) {
                    float2 rr = *(const float2*)&resid[obase + n];
                    vx += rr.x; vy += rr.y;
                }
                if (OUT_HALF) {
                    __half2* op = (__half2*)((__half*)Cout + obase + n);
                    *op = __floats2half2_rn(vx, vy);
                } else {
                    *(float2*)((float*)Cout + obase + n) = make_float2(vx, vy);
                }
            }
        }
    }
}

// ---------------------------------------------------------------------------
// Fused softmax + bilinear sampling — 2 queries/warp, 4 points in parallel,
// 8 channels per lane (LDG.128 gathers).
// Warp gw: pair = gw>>3, head = gw&7; lane half (bit4) = query.
// Within 16-lane half: g4 = hl>>2 (point in level), cq = hl&3 (channel octet).
// ---------------------------------------------------------------------------
#define SHFL16(v, s) __shfl_sync(0xffffffffu, (v), (s), 16)

__device__ __forceinline__ void corner_acc(float (&acc)[8], const uint4* p,
                                           float wgt) {
    uint4 u = *p;
    float2 f0 = __half22float2(*reinterpret_cast<__half2*>(&u.x));
    float2 f1 = __half22float2(*reinterpret_cast<__half2*>(&u.y));
    float2 f2 = __half22float2(*reinterpret_cast<__half2*>(&u.z));
    float2 f3 = __half22float2(*reinterpret_cast<__half2*>(&u.w));
    acc[0] = fmaf(wgt, f0.x, acc[0]); acc[1] = fmaf(wgt, f0.y, acc[1]);
    acc[2] = fmaf(wgt, f1.x, acc[2]); acc[3] = fmaf(wgt, f1.y, acc[3]);
    acc[4] = fmaf(wgt, f2.x, acc[4]); acc[5] = fmaf(wgt, f2.y, acc[5]);
    acc[6] = fmaf(wgt, f3.x, acc[6]); acc[7] = fmaf(wgt, f3.y, acc[7]);
}

__global__ __launch_bounds__(512)
void msda_sample(const float* __restrict__ rp,
                 const __half* __restrict__ val,
                 const __half* __restrict__ proj,
                 __half* __restrict__ msda)
{
    const int gw   = (blockIdx.x * 512 + threadIdx.x) >> 5;
    const int lane = threadIdx.x & 31;
    const int pair = gw >> 3;
    const int h    = gw & 7;
    const int hl   = lane & 15;            // lane within query-half
    const int bq   = pair * 2 + (lane >> 4);
    const int g4   = hl >> 2;              // 0..3 point group
    const int cq   = hl & 3;               // channel octet (8 ch)
    const int b    = bq / LQc;

    const __half* prow = proj + bq * PROJW;
    float off0 = __half2float(prow[h * 32 + hl]);        // offsets 0..15
    float off1 = __half2float(prow[h * 32 + 16 + hl]);   // offsets 16..31
    float lg   = __half2float(prow[256 + h * 16 + hl]);  // 16 logits
    float rpv  = 0.f;
    if (hl < 8) {
        rpv = rp[bq * (Lc * 2) + hl];
        rpv = fminf(fmaxf(rpv, 1e-5f), 1.f - 1e-5f);
    }

    // Softmax over 16 logits (xor 1..8 stays within each 16-lane half)
    float mx = lg;
    #pragma unroll
    for (int o = 8; o > 0; o >>= 1)
        mx = fmaxf(mx, __shfl_xor_sync(0xffffffffu, mx, o));
    float e = __expf(lg - mx);
    float sum = e;
    #pragma unroll
    for (int o = 8; o > 0; o >>= 1)
        sum += __shfl_xor_sync(0xffffffffu, sum, o);
    float attn_val = e / sum;

    constexpr int HH[4] = {100, 50, 25, 13};
    constexpr int ST[4] = {0, 10000, 12500, 13125};

    // uint4 units: 256 halves/pixel = 32 uint4; lane covers 8 channels
    const uint4* vb = (const uint4*)val + (b * LVc) * 32 + h * 4 + cq;

    float acc[8];
    #pragma unroll
    for (int j = 0; j < 8; j++) acc[j] = 0.f;

    #pragma unroll
    for (int l = 0; l < Lc; l++) {
        const int   Wl = HH[l];
        const int   st = ST[l];
        const float fW = (float)HH[l];

        float rpx = SHFL16(rpv, 2 * l);
        float rpy = SHFL16(rpv, 2 * l + 1);

        const int oidx = l * 8 + 2 * g4;   // offset-pair index for this point
        float offx, offy;
        if (l < 2) { offx = SHFL16(off0, oidx);      offy = SHFL16(off0, oidx + 1); }
        else       { offx = SHFL16(off1, oidx - 16); offy = SHFL16(off1, oidx - 15); }
        float a = SHFL16(attn_val, l * 4 + g4);

        float x = fmaf(rpx, fW, offx) - 0.5f;
        float y = fmaf(rpy, fW, offy) - 0.5f;
        float x0f = floorf(x), y0f = floorf(y);
        int x0 = (int)x0f, y0 = (int)y0f;
        float wx = x - x0f, wy = y - y0f;

        float w00 = a * (1.f - wy) * (1.f - wx);
        float w01 = a * (1.f - wy) * wx;
        float w10 = a * wy * (1.f - wx);
        float w11 = a * wy * wx;

        int x1 = x0 + 1, y1 = y0 + 1;
        bool vx0 = (x0 >= 0) & (x0 < Wl);
        bool vx1 = (x1 >= 0) & (x1 < Wl);
        bool vy0 = (y0 >= 0) & (y0 < Wl);
        bool vy1 = (y1 >= 0) & (y1 < Wl);

        int row0 = (st + y0 * Wl) * 32;
        int row1 = row0 + Wl * 32;

        if (vy0 & vx0) corner_acc(acc, vb + row0 + x0 * 32, w00);
        if (vy0 & vx1) corner_acc(acc, vb + row0 + x1 * 32, w01);
        if (vy1 & vx0) corner_acc(acc, vb + row1 + x0 * 32, w10);
        if (vy1 & vx1) corner_acc(acc, vb + row1 + x1 * 32, w11);
    }

    // Reduce across the 4 point-groups (hl bits 2,3 -> xor 4, xor 8)
    #pragma unroll
    for (int j = 0; j < 8; j++) {
        acc[j] += __shfl_xor_sync(0xffffffffu, acc[j], 4);
        acc[j] += __shfl_xor_sync(0xffffffffu, acc[j], 8);
    }

    if (g4 == 0) {
        uint4 o;
        o.x = pack_h2(acc[0], acc[1]);
        o.y = pack_h2(acc[2], acc[3]);
        o.z = pack_h2(acc[4], acc[5]);
        o.w = pack_h2(acc[6], acc[7]);
        ((uint4*)msda)[bq * 32 + h * 4 + cq] = o;
    }
}

// ---------------------------------------------------------------------------
extern "C" void kernel_launch(void* const* d_in, const int* in_sizes, int n_in,
                              void* d_out, int out_size)
{
    const float* query = (const float*)d_in[0];   // (LQ, B, C)
    const float* rp    = (const float*)d_in[1];   // (B, LQ, L, 2)
    const float* value = (const float*)d_in[2];   // (LV, B, C)
    const float* Wv    = (const float*)d_in[5];
    const float* bv    = (const float*)d_in[6];
    const float* Woff  = (const float*)d_in[7];
    const float* boff  = (const float*)d_in[8];
    const float* Wattn = (const float*)d_in[9];
    const float* battn = (const float*)d_in[10];
    const float* Wo    = (const float*)d_in[11];
    const float* bo    = (const float*)d_in[12];
    float* out = (float*)d_out;

    __half *valp, *msdap, *projp;
    float *wcatp, *bcatp;
    cudaGetSymbolAddress((void**)&valp,  g_val);
    cudaGetSymbolAddress((void**)&projp, g_proj);
    cudaGetSymbolAddress((void**)&msdap, g_msda);
    cudaGetSymbolAddress((void**)&wcatp, g_wcat);
    cudaGetSymbolAddress((void**)&bcatp, g_bcat);

    const int gm = (Mrows + 127) / 128;   // 208

    // 0) concat Woff||Wattn, boff||battn
    concat_w<<<(Cc * PROJW + 255) / 256, 256>>>(Woff, boff, Wattn, battn,
                                                wcatp, bcatp);
    // 1) value projection -> fp16 g_val
    hgemm_tc<true, 0, true, false><<<dim3(gm, 2), 256>>>(
        value, Wv, bv, valp, Mrows, LVc, 256, 256, nullptr);
    // 2) fused offset+attn projection -> fp16 g_proj
    hgemm_tc<true, 0, true, false><<<dim3(gm, 3), 256>>>(
        query, wcatp, bcatp, projp, Mrows, LQc, PROJW, PROJW, nullptr);
    // 3) softmax + bilinear sampling -> fp16 g_msda (2 queries per warp)
    msda_sample<<<(Mrows / 2 * NHc) / 16, 512>>>(rp, valp, projp, msdap);
    // 4) output projection + bias + residual -> d_out (A in fp16)
    hgemm_tc<false, 1, false, true><<<dim3(gm, 2), 256>>>(
        msdap, Wo, bo, out, Mrows, LQc, 256, 256, query);
}

// round 10
// speedup vs baseline: 2.8808x; 1.0299x over previous
#include <cuda_runtime.h>
#include <cuda_fp16.h>
#include <math.h>
#include <stdint.h>

// ---------------------------------------------------------------------------
// Problem constants (fixed instance)
// ---------------------------------------------------------------------------
constexpr int Bc  = 2;
constexpr int Cc  = 256;
constexpr int NHc = 8;
constexpr int Lc  = 4;
constexpr int Pc  = 4;
constexpr int LVc = 13294;       // 100*100 + 50*50 + 25*25 + 13*13
constexpr int LQc = 13294;
constexpr int Mrows = Bc * LQc;  // 26588
constexpr int PROJW = NHc * Lc * Pc * 2 + NHc * Lc * Pc; // 384

// Scratch (device globals; no allocation allowed)
__device__ __half g_val [Bc * LVc * Cc];    // [b][lv][c]  fp16
__device__ __half g_proj[Bc * LQc * PROJW]; // [b][q][384] fp16
__device__ __half g_msda[Bc * LQc * Cc];    // [b][q][c]   fp16
__device__ float  g_wcat[Cc * PROJW];       // Woff || Wattn
__device__ float  g_bcat[PROJW];            // boff || battn

// ---------------------------------------------------------------------------
// fp16 MMA helpers
// ---------------------------------------------------------------------------
__device__ __forceinline__ uint32_t pack_h2(float a, float b) {
    __half2 h = __floats2half2_rn(a, b);
    return *reinterpret_cast<uint32_t*>(&h);
}
__device__ __forceinline__ void ldmatrix_x4(uint32_t (&r)[4], uint32_t saddr) {
    asm volatile("ldmatrix.sync.aligned.m8n8.x4.shared.b16 {%0,%1,%2,%3}, [%4];"
                 : "=r"(r[0]), "=r"(r[1]), "=r"(r[2]), "=r"(r[3])
                 : "r"(saddr));
}
__device__ __forceinline__ void mma_f16(float (&d)[4],
                                        const uint32_t (&a)[4],
                                        const uint32_t b0, const uint32_t b1) {
    asm volatile(
        "mma.sync.aligned.m16n8k16.row.col.f32.f16.f16.f32 "
        "{%0,%1,%2,%3}, {%4,%5,%6,%7}, {%8,%9}, {%0,%1,%2,%3};"
        : "+f"(d[0]), "+f"(d[1]), "+f"(d[2]), "+f"(d[3])
        : "r"(a[0]), "r"(a[1]), "r"(a[2]), "r"(a[3]), "r"(b0), "r"(b1));
}

// ---------------------------------------------------------------------------
// Weight/bias concat: g_wcat[k][n] = n<256 ? Woff[k][n] : Wattn[k][n-256]
// ---------------------------------------------------------------------------
__global__ void concat_w(const float* __restrict__ Woff,
                         const float* __restrict__ boff,
                         const float* __restrict__ Wattn,
                         const float* __restrict__ battn,
                         float* __restrict__ wcat, float* __restrict__ bcat)
{
    int i = blockIdx.x * 256 + threadIdx.x;
    if (i < Cc * PROJW) {
        int k = i / PROJW, n = i - k * PROJW;
        wcat[i] = (n < 256) ? Woff[k * 256 + n] : Wattn[k * 128 + n - 256];
    }
    if (i < PROJW) bcat[i] = (i < 256) ? boff[i] : battn[i - 256];
}

// ---------------------------------------------------------------------------
// Tensor-core FP16 GEMM (fp32 accum): Cout = A(MxK=256)*W(256xN)+bias(+resid)
//   A_ILV: A row m at A[(s*Bc+b)*256+k]. OUT_MODE 1: residual + interleaved
//   output. OUT_HALF: __half output. A_HALF: A is __half (direct copy staging).
// BM=128, BN=128, BK=32. 8 warps (2x4), warp tile 64x32, m16n8k16.
// ---------------------------------------------------------------------------
template<bool A_ILV, int OUT_MODE, bool OUT_HALF, bool A_HALF>
__global__ __launch_bounds__(256)
void hgemm_tc(const void* __restrict__ Ain, const float* __restrict__ W,
              const float* __restrict__ bias, void* __restrict__ Cout,
              int M, int Lseq, int ldw, int ldc,
              const float* __restrict__ resid)
{
    __shared__ __half    As[2][128][40];    // [stage][m][k-half]
    __shared__ uint32_t  Bp[2][16][136];    // [stage][kpair][n] packed half2

    const int tid  = threadIdx.x;
    const int warp = tid >> 5;
    const int lane = tid & 31;
    const int wm = warp >> 2;          // 0..1
    const int wn = warp & 3;           // 0..3
    const int m0 = blockIdx.x * 128;
    const int n0 = blockIdx.y * 128;
    const int qr = lane >> 2;          // 0..7
    const int qc = lane & 3;           // 0..3

    // ---- staging slots ----
    int arow[2], ac8[2];
    const void* aptr[2];
    #pragma unroll
    for (int r = 0; r < 2; r++) {
        int idx = tid + r * 256;
        arow[r] = idx >> 2;            // 0..127
        ac8[r]  = (idx & 3) * 8;       // element offset in k-tile
        int m = m0 + arow[r];
        if (m < M) {
            int off;
            if (A_ILV) { int b = m / Lseq; int s = m - b * Lseq;
                         off = (s * Bc + b) * Cc; }
            else       { off = m * Cc; }
            if (A_HALF) aptr[r] = (const __half*)Ain + off;
            else        aptr[r] = (const float*)Ain + off;
        } else aptr[r] = nullptr;
    }
    int wkp[2], wn4[2];
    #pragma unroll
    for (int r = 0; r < 2; r++) {
        int idx = tid + r * 256;
        wkp[r] = idx >> 5;             // 0..15
        wn4[r] = (idx & 31) * 4;       // 0..124
    }
    const float* wbase = W + n0;

    float acc[4][4][4];
    #pragma unroll
    for (int mt = 0; mt < 4; mt++)
        #pragma unroll
        for (int nt = 0; nt < 4; nt++)
            #pragma unroll
            for (int c = 0; c < 4; c++) acc[mt][nt][c] = 0.f;

    const float4 f4z = make_float4(0.f, 0.f, 0.f, 0.f);

    float4 na[2][2], nw[2][2];
    uint4 ua[2];
    auto load_tile = [&](int kb) {
        #pragma unroll
        for (int r = 0; r < 2; r++) {
            if (A_HALF) {
                if (aptr[r]) ua[r] = *(const uint4*)((const __half*)aptr[r] + kb + ac8[r]);
                else         ua[r] = make_uint4(0, 0, 0, 0);
            } else {
                if (aptr[r]) {
                    na[r][0] = *(const float4*)((const float*)aptr[r] + kb + ac8[r]);
                    na[r][1] = *(const float4*)((const float*)aptr[r] + kb + ac8[r] + 4);
                } else { na[r][0] = f4z; na[r][1] = f4z; }
            }
            nw[r][0] = *(const float4*)(wbase + (kb + 2 * wkp[r]    ) * ldw + wn4[r]);
            nw[r][1] = *(const float4*)(wbase + (kb + 2 * wkp[r] + 1) * ldw + wn4[r]);
        }
    };
    auto store_tile = [&](int st) {
        #pragma unroll
        for (int r = 0; r < 2; r++) {
            if (A_HALF) {
                *(uint4*)&As[st][arow[r]][ac8[r]] = ua[r];
            } else {
                uint4 a4;
                a4.x = pack_h2(na[r][0].x, na[r][0].y);
                a4.y = pack_h2(na[r][0].z, na[r][0].w);
                a4.z = pack_h2(na[r][1].x, na[r][1].y);
                a4.w = pack_h2(na[r][1].z, na[r][1].w);
                *(uint4*)&As[st][arow[r]][ac8[r]] = a4;
            }
            uint4 w4;
            w4.x = pack_h2(nw[r][0].x, nw[r][1].x);
            w4.y = pack_h2(nw[r][0].y, nw[r][1].y);
            w4.z = pack_h2(nw[r][0].z, nw[r][1].z);
            w4.w = pack_h2(nw[r][0].w, nw[r][1].w);
            *(uint4*)&Bp[st][wkp[r]][wn4[r]] = w4;
        }
    };

    load_tile(0);
    store_tile(0);
    __syncthreads();

    #pragma unroll 1
    for (int kk = 0; kk < Cc / 32; kk++) {
        const int cur = kk & 1;
        if (kk < Cc / 32 - 1) load_tile((kk + 1) * 32);

        #pragma unroll
        for (int ks = 0; ks < 32; ks += 16) {
            uint32_t afr[4][4];
            #pragma unroll
            for (int mt = 0; mt < 4; mt++) {
                int rowb = wm * 64 + mt * 16;
                int row = rowb + (lane & 7) + ((lane >> 3) & 1) * 8;
                int col = ks + (lane >> 4) * 8;
                uint32_t sa = (uint32_t)__cvta_generic_to_shared(&As[cur][row][col]);
                ldmatrix_x4(afr[mt], sa);
            }
            uint32_t bfr[4][2];
            #pragma unroll
            for (int nt = 0; nt < 4; nt++) {
                int col = wn * 32 + nt * 8 + qr;
                bfr[nt][0] = Bp[cur][ks / 2 + qc    ][col];
                bfr[nt][1] = Bp[cur][ks / 2 + qc + 4][col];
            }
            #pragma unroll
            for (int mt = 0; mt < 4; mt++)
                #pragma unroll
                for (int nt = 0; nt < 4; nt++)
                    mma_f16(acc[mt][nt], afr[mt], bfr[nt][0], bfr[nt][1]);
        }

        if (kk < Cc / 32 - 1) {
            store_tile(cur ^ 1);
            __syncthreads();
        }
    }

    // ---- epilogue ----
    float2 bvals[4];
    #pragma unroll
    for (int nt = 0; nt < 4; nt++) {
        int n = n0 + wn * 32 + nt * 8 + qc * 2;
        bvals[nt] = *(const float2*)&bias[n];
    }

    #pragma unroll
    for (int mt = 0; mt < 4; mt++) {
        #pragma unroll
        for (int hrow = 0; hrow < 2; hrow++) {
            int m = m0 + wm * 64 + mt * 16 + qr + hrow * 8;
            if (m >= M) continue;
            int obase;
            if (OUT_MODE == 1) {
                int b = m / Lseq; int s = m - b * Lseq;
                obase = (s * Bc + b) * Cc;
            } else {
                obase = m * ldc;
            }
            #pragma unroll
            for (int nt = 0; nt < 4; nt++) {
                int n = n0 + wn * 32 + nt * 8 + qc * 2;
                float vx = acc[mt][nt][hrow * 2 + 0] + bvals[nt].x;
                float vy = acc[mt][nt][hrow * 2 + 1] + bvals[nt].y;
                if (OUT_MODE == 1) {
                    float2 rr = *(const float2*)&resid[obase + n];
                    vx += rr.x; vy += rr.y;
                }
                if (OUT_HALF) {
                    __half2* op = (__half2*)((__half*)Cout + obase + n);
                    *op = __floats2half2_rn(vx, vy);
                } else {
                    *(float2*)((float*)Cout + obase + n) = make_float2(vx, vy);
                }
            }
        }
    }
}

// ---------------------------------------------------------------------------
// Fused softmax + bilinear sampling — 2 queries/warp, 4 points in parallel,
// 8 channels per lane (LDG.128), per-level HFMA2 corner accumulation.
// Warp gw: pair = gw>>3, head = gw&7; lane half (bit4) = query.
// Within 16-lane half: g4 = hl>>2 (point in level), cq = hl&3 (channel octet).
// ---------------------------------------------------------------------------
#define SHFL16(v, s) __shfl_sync(0xffffffffu, (v), (s), 16)

__device__ __forceinline__ void corner_acc_h2(__half2 (&hacc)[4], const uint4* p,
                                              __half2 w) {
    uint4 u = *p;
    hacc[0] = __hfma2(*reinterpret_cast<__half2*>(&u.x), w, hacc[0]);
    hacc[1] = __hfma2(*reinterpret_cast<__half2*>(&u.y), w, hacc[1]);
    hacc[2] = __hfma2(*reinterpret_cast<__half2*>(&u.z), w, hacc[2]);
    hacc[3] = __hfma2(*reinterpret_cast<__half2*>(&u.w), w, hacc[3]);
}

__global__ __launch_bounds__(512)
void msda_sample(const float* __restrict__ rp,
                 const __half* __restrict__ val,
                 const __half* __restrict__ proj,
                 __half* __restrict__ msda)
{
    const int gw   = (blockIdx.x * 512 + threadIdx.x) >> 5;
    const int lane = threadIdx.x & 31;
    const int pair = gw >> 3;
    const int h    = gw & 7;
    const int hl   = lane & 15;            // lane within query-half
    const int bq   = pair * 2 + (lane >> 4);
    const int g4   = hl >> 2;              // 0..3 point group
    const int cq   = hl & 3;               // channel octet (8 ch)
    const int b    = bq / LQc;

    const __half* prow = proj + bq * PROJW;
    float off0 = __half2float(prow[h * 32 + hl]);        // offsets 0..15
    float off1 = __half2float(prow[h * 32 + 16 + hl]);   // offsets 16..31
    float lg   = __half2float(prow[256 + h * 16 + hl]);  // 16 logits
    float rpv  = 0.f;
    if (hl < 8) {
        rpv = rp[bq * (Lc * 2) + hl];
        rpv = fminf(fmaxf(rpv, 1e-5f), 1.f - 1e-5f);
    }

    // Softmax over 16 logits (xor 1..8 stays within each 16-lane half)
    float mx = lg;
    #pragma unroll
    for (int o = 8; o > 0; o >>= 1)
        mx = fmaxf(mx, __shfl_xor_sync(0xffffffffu, mx, o));
    float e = __expf(lg - mx);
    float sum = e;
    #pragma unroll
    for (int o = 8; o > 0; o >>= 1)
        sum += __shfl_xor_sync(0xffffffffu, sum, o);
    float attn_val = e / sum;

    constexpr int HH[4] = {100, 50, 25, 13};
    constexpr int ST[4] = {0, 10000, 12500, 13125};

    // uint4 units: 256 halves/pixel = 32 uint4; lane covers 8 channels
    const uint4* vb = (const uint4*)val + (b * LVc) * 32 + h * 4 + cq;

    float acc[8];
    #pragma unroll
    for (int j = 0; j < 8; j++) acc[j] = 0.f;

    #pragma unroll
    for (int l = 0; l < Lc; l++) {
        const int   Wl = HH[l];
        const int   st = ST[l];
        const float fW = (float)HH[l];

        float rpx = SHFL16(rpv, 2 * l);
        float rpy = SHFL16(rpv, 2 * l + 1);

        const int oidx = l * 8 + 2 * g4;   // offset-pair index for this point
        float offx, offy;
        if (l < 2) { offx = SHFL16(off0, oidx);      offy = SHFL16(off0, oidx + 1); }
        else       { offx = SHFL16(off1, oidx - 16); offy = SHFL16(off1, oidx - 15); }
        float a = SHFL16(attn_val, l * 4 + g4);

        float x = fmaf(rpx, fW, offx) - 0.5f;
        float y = fmaf(rpy, fW, offy) - 0.5f;
        float x0f = floorf(x), y0f = floorf(y);
        int x0 = (int)x0f, y0 = (int)y0f;
        float wx = x - x0f, wy = y - y0f;

        float w00 = a * (1.f - wy) * (1.f - wx);
        float w01 = a * (1.f - wy) * wx;
        float w10 = a * wy * (1.f - wx);
        float w11 = a * wy * wx;

        int x1 = x0 + 1, y1 = y0 + 1;
        bool vx0 = (x0 >= 0) & (x0 < Wl);
        bool vx1 = (x1 >= 0) & (x1 < Wl);
        bool vy0 = (y0 >= 0) & (y0 < Wl);
        bool vy1 = (y1 >= 0) & (y1 < Wl);

        int row0 = (st + y0 * Wl) * 32;
        int row1 = row0 + Wl * 32;

        // Per-level fp16 corner accumulation (4 HFMA2 per corner)
        __half2 hz = __float2half2_rn(0.f);
        __half2 hacc[4] = {hz, hz, hz, hz};
        if (vy0 & vx0) corner_acc_h2(hacc, vb + row0 + x0 * 32, __float2half2_rn(w00));
        if (vy0 & vx1) corner_acc_h2(hacc, vb + row0 + x1 * 32, __float2half2_rn(w01));
        if (vy1 & vx0) corner_acc_h2(hacc, vb + row1 + x0 * 32, __float2half2_rn(w10));
        if (vy1 & vx1) corner_acc_h2(hacc, vb + row1 + x1 * 32, __float2half2_rn(w11));

        // Fold level partial into fp32 master accumulator
        #pragma unroll
        for (int j = 0; j < 4; j++) {
            float2 t = __half22float2(hacc[j]);
            acc[2 * j]     += t.x;
            acc[2 * j + 1] += t.y;
        }
    }

    // Reduce across the 4 point-groups (hl bits 2,3 -> xor 4, xor 8)
    #pragma unroll
    for (int j = 0; j < 8; j++) {
        acc[j] += __shfl_xor_sync(0xffffffffu, acc[j], 4);
        acc[j] += __shfl_xor_sync(0xffffffffu, acc[j], 8);
    }

    if (g4 == 0) {
        uint4 o;
        o.x = pack_h2(acc[0], acc[1]);
        o.y = pack_h2(acc[2], acc[3]);
        o.z = pack_h2(acc[4], acc[5]);
        o.w = pack_h2(acc[6], acc[7]);
        ((uint4*)msda)[bq * 32 + h * 4 + cq] = o;
    }
}

// ---------------------------------------------------------------------------
extern "C" void kernel_launch(void* const* d_in, const int* in_sizes, int n_in,
                              void* d_out, int out_size)
{
    const float* query = (const float*)d_in[0];   // (LQ, B, C)
    const float* rp    = (const float*)d_in[1];   // (B, LQ, L, 2)
    const float* value = (const float*)d_in[2];   // (LV, B, C)
    const float* Wv    = (const float*)d_in[5];
    const float* bv    = (const float*)d_in[6];
    const float* Woff  = (const float*)d_in[7];
    const float* boff  = (const float*)d_in[8];
    const float* Wattn = (const float*)d_in[9];
    const float* battn = (const float*)d_in[10];
    const float* Wo    = (const float*)d_in[11];
    const float* bo    = (const float*)d_in[12];
    float* out = (float*)d_out;

    __half *valp, *msdap, *projp;
    float *wcatp, *bcatp;
    cudaGetSymbolAddress((void**)&valp,  g_val);
    cudaGetSymbolAddress((void**)&projp, g_proj);
    cudaGetSymbolAddress((void**)&msdap, g_msda);
    cudaGetSymbolAddress((void**)&wcatp, g_wcat);
    cudaGetSymbolAddress((void**)&bcatp, g_bcat);

    const int gm = (Mrows + 127) / 128;   // 208

    // 0) concat Woff||Wattn, boff||battn
    concat_w<<<(Cc * PROJW + 255) / 256, 256>>>(Woff, boff, Wattn, battn,
                                                wcatp, bcatp);
    // 1) value projection -> fp16 g_val
    hgemm_tc<true, 0, true, false><<<dim3(gm, 2), 256>>>(
        value, Wv, bv, valp, Mrows, LVc, 256, 256, nullptr);
    // 2) fused offset+attn projection -> fp16 g_proj
    hgemm_tc<true, 0, true, false><<<dim3(gm, 3), 256>>>(
        query, wcatp, bcatp, projp, Mrows, LQc, PROJW, PROJW, nullptr);
    // 3) softmax + bilinear sampling -> fp16 g_msda (2 queries per warp)
    msda_sample<<<(Mrows / 2 * NHc) / 16, 512>>>(rp, valp, projp, msdap);
    // 4) output projection + bias + residual -> d_out (A in fp16)
    hgemm_tc<false, 1, false, true><<<dim3(gm, 2), 256>>>(
        msdap, Wo, bo, out, Mrows, LQc, 256, 256, query);
}

// round 11
// speedup vs baseline: 2.9416x; 1.0211x over previous
#include <cuda_runtime.h>
#include <cuda_fp16.h>
#include <math.h>
#include <stdint.h>

// ---------------------------------------------------------------------------
// Problem constants (fixed instance)
// ---------------------------------------------------------------------------
constexpr int Bc  = 2;
constexpr int Cc  = 256;
constexpr int NHc = 8;
constexpr int Lc  = 4;
constexpr int Pc  = 4;
constexpr int LVc = 13294;       // 100*100 + 50*50 + 25*25 + 13*13
constexpr int LQc = 13294;
constexpr int Mrows = Bc * LQc;  // 26588
constexpr int PROJW = NHc * Lc * Pc * 2 + NHc * Lc * Pc; // 384

// Scratch (device globals; no allocation allowed)
__device__ __half g_val [Bc * LVc * Cc];    // [b][lv][c]  fp16
__device__ __half g_proj[Bc * LQc * PROJW]; // [b][q][384] fp16
__device__ __half g_msda[Bc * LQc * Cc];    // [b][q][c]   fp16
__device__ float  g_wcat[Cc * PROJW];       // Woff || Wattn
__device__ float  g_bcat[PROJW];            // boff || battn

// ---------------------------------------------------------------------------
// fp16 MMA helpers
// ---------------------------------------------------------------------------
__device__ __forceinline__ uint32_t pack_h2(float a, float b) {
    __half2 h = __floats2half2_rn(a, b);
    return *reinterpret_cast<uint32_t*>(&h);
}
__device__ __forceinline__ void ldmatrix_x4(uint32_t (&r)[4], uint32_t saddr) {
    asm volatile("ldmatrix.sync.aligned.m8n8.x4.shared.b16 {%0,%1,%2,%3}, [%4];"
                 : "=r"(r[0]), "=r"(r[1]), "=r"(r[2]), "=r"(r[3])
                 : "r"(saddr));
}
__device__ __forceinline__ void mma_f16(float (&d)[4],
                                        const uint32_t (&a)[4],
                                        const uint32_t b0, const uint32_t b1) {
    asm volatile(
        "mma.sync.aligned.m16n8k16.row.col.f32.f16.f16.f32 "
        "{%0,%1,%2,%3}, {%4,%5,%6,%7}, {%8,%9}, {%0,%1,%2,%3};"
        : "+f"(d[0]), "+f"(d[1]), "+f"(d[2]), "+f"(d[3])
        : "r"(a[0]), "r"(a[1]), "r"(a[2]), "r"(a[3]), "r"(b0), "r"(b1));
}

// ---------------------------------------------------------------------------
// Weight/bias concat: g_wcat[k][n] = n<256 ? Woff[k][n] : Wattn[k][n-256]
// ---------------------------------------------------------------------------
__global__ void concat_w(const float* __restrict__ Woff,
                         const float* __restrict__ boff,
                         const float* __restrict__ Wattn,
                         const float* __restrict__ battn,
                         float* __restrict__ wcat, float* __restrict__ bcat)
{
    int i = blockIdx.x * 256 + threadIdx.x;
    if (i < Cc * PROJW) {
        int k = i / PROJW, n = i - k * PROJW;
        wcat[i] = (n < 256) ? Woff[k * 256 + n] : Wattn[k * 128 + n - 256];
    }
    if (i < PROJW) bcat[i] = (i < 256) ? boff[i] : battn[i - 256];
}

// ---------------------------------------------------------------------------
// Tensor-core FP16 GEMM (fp32 accum): Cout = A(MxK=256)*W(256xN)+bias(+resid)
//   A_ILV: A row m at A[(s*Bc+b)*256+k]. OUT_MODE 1: residual + interleaved
//   output. OUT_HALF: __half output. A_HALF: A is __half (direct copy staging).
// BM=128, BN=128, BK=32. 8 warps (2x4), warp tile 64x32, m16n8k16.
// ---------------------------------------------------------------------------
template<bool A_ILV, int OUT_MODE, bool OUT_HALF, bool A_HALF>
__global__ __launch_bounds__(256)
void hgemm_tc(const void* __restrict__ Ain, const float* __restrict__ W,
              const float* __restrict__ bias, void* __restrict__ Cout,
              int M, int Lseq, int ldw, int ldc,
              const float* __restrict__ resid)
{
    __shared__ __half    As[2][128][40];    // [stage][m][k-half]
    __shared__ uint32_t  Bp[2][16][136];    // [stage][kpair][n] packed half2

    const int tid  = threadIdx.x;
    const int warp = tid >> 5;
    const int lane = tid & 31;
    const int wm = warp >> 2;          // 0..1
    const int wn = warp & 3;           // 0..3
    const int m0 = blockIdx.x * 128;
    const int n0 = blockIdx.y * 128;
    const int qr = lane >> 2;          // 0..7
    const int qc = lane & 3;           // 0..3

    // ---- staging slots ----
    int arow[2], ac8[2];
    const void* aptr[2];
    #pragma unroll
    for (int r = 0; r < 2; r++) {
        int idx = tid + r * 256;
        arow[r] = idx >> 2;            // 0..127
        ac8[r]  = (idx & 3) * 8;       // element offset in k-tile
        int m = m0 + arow[r];
        if (m < M) {
            int off;
            if (A_ILV) { int b = m / Lseq; int s = m - b * Lseq;
                         off = (s * Bc + b) * Cc; }
            else       { off = m * Cc; }
            if (A_HALF) aptr[r] = (const __half*)Ain + off;
            else        aptr[r] = (const float*)Ain + off;
        } else aptr[r] = nullptr;
    }
    int wkp[2], wn4[2];
    #pragma unroll
    for (int r = 0; r < 2; r++) {
        int idx = tid + r * 256;
        wkp[r] = idx >> 5;             // 0..15
        wn4[r] = (idx & 31) * 4;       // 0..124
    }
    const float* wbase = W + n0;

    float acc[4][4][4];
    #pragma unroll
    for (int mt = 0; mt < 4; mt++)
        #pragma unroll
        for (int nt = 0; nt < 4; nt++)
            #pragma unroll
            for (int c = 0; c < 4; c++) acc[mt][nt][c] = 0.f;

    const float4 f4z = make_float4(0.f, 0.f, 0.f, 0.f);

    float4 na[2][2], nw[2][2];
    uint4 ua[2];
    auto load_tile = [&](int kb) {
        #pragma unroll
        for (int r = 0; r < 2; r++) {
            if (A_HALF) {
                if (aptr[r]) ua[r] = *(const uint4*)((const __half*)aptr[r] + kb + ac8[r]);
                else         ua[r] = make_uint4(0, 0, 0, 0);
            } else {
                if (aptr[r]) {
                    na[r][0] = *(const float4*)((const float*)aptr[r] + kb + ac8[r]);
                    na[r][1] = *(const float4*)((const float*)aptr[r] + kb + ac8[r] + 4);
                } else { na[r][0] = f4z; na[r][1] = f4z; }
            }
            nw[r][0] = *(const float4*)(wbase + (kb + 2 * wkp[r]    ) * ldw + wn4[r]);
            nw[r][1] = *(const float4*)(wbase + (kb + 2 * wkp[r] + 1) * ldw + wn4[r]);
        }
    };
    auto store_tile = [&](int st) {
        #pragma unroll
        for (int r = 0; r < 2; r++) {
            if (A_HALF) {
                *(uint4*)&As[st][arow[r]][ac8[r]] = ua[r];
            } else {
                uint4 a4;
                a4.x = pack_h2(na[r][0].x, na[r][0].y);
                a4.y = pack_h2(na[r][0].z, na[r][0].w);
                a4.z = pack_h2(na[r][1].x, na[r][1].y);
                a4.w = pack_h2(na[r][1].z, na[r][1].w);
                *(uint4*)&As[st][arow[r]][ac8[r]] = a4;
            }
            uint4 w4;
            w4.x = pack_h2(nw[r][0].x, nw[r][1].x);
            w4.y = pack_h2(nw[r][0].y, nw[r][1].y);
            w4.z = pack_h2(nw[r][0].z, nw[r][1].z);
            w4.w = pack_h2(nw[r][0].w, nw[r][1].w);
            *(uint4*)&Bp[st][wkp[r]][wn4[r]] = w4;
        }
    };

    load_tile(0);
    store_tile(0);
    __syncthreads();

    #pragma unroll 1
    for (int kk = 0; kk < Cc / 32; kk++) {
        const int cur = kk & 1;
        if (kk < Cc / 32 - 1) load_tile((kk + 1) * 32);

        #pragma unroll
        for (int ks = 0; ks < 32; ks += 16) {
            uint32_t afr[4][4];
            #pragma unroll
            for (int mt = 0; mt < 4; mt++) {
                int rowb = wm * 64 + mt * 16;
                int row = rowb + (lane & 7) + ((lane >> 3) & 1) * 8;
                int col = ks + (lane >> 4) * 8;
                uint32_t sa = (uint32_t)__cvta_generic_to_shared(&As[cur][row][col]);
                ldmatrix_x4(afr[mt], sa);
            }
            uint32_t bfr[4][2];
            #pragma unroll
            for (int nt = 0; nt < 4; nt++) {
                int col = wn * 32 + nt * 8 + qr;
                bfr[nt][0] = Bp[cur][ks / 2 + qc    ][col];
                bfr[nt][1] = Bp[cur][ks / 2 + qc + 4][col];
            }
            #pragma unroll
            for (int mt = 0; mt < 4; mt++)
                #pragma unroll
                for (int nt = 0; nt < 4; nt++)
                    mma_f16(acc[mt][nt], afr[mt], bfr[nt][0], bfr[nt][1]);
        }

        if (kk < Cc / 32 - 1) {
            store_tile(cur ^ 1);
            __syncthreads();
        }
    }

    // ---- epilogue ----
    float2 bvals[4];
    #pragma unroll
    for (int nt = 0; nt < 4; nt++) {
        int n = n0 + wn * 32 + nt * 8 + qc * 2;
        bvals[nt] = *(const float2*)&bias[n];
    }

    #pragma unroll
    for (int mt = 0; mt < 4; mt++) {
        #pragma unroll
        for (int hrow = 0; hrow < 2; hrow++) {
            int m = m0 + wm * 64 + mt * 16 + qr + hrow * 8;
            if (m >= M) continue;
            int obase;
            if (OUT_MODE == 1) {
                int b = m / Lseq; int s = m - b * Lseq;
                obase = (s * Bc + b) * Cc;
            } else {
                obase = m * ldc;
            }
            #pragma unroll
            for (int nt = 0; nt < 4; nt++) {
                int n = n0 + wn * 32 + nt * 8 + qc * 2;
                float vx = acc[mt][nt][hrow * 2 + 0] + bvals[nt].x;
                float vy = acc[mt][nt][hrow * 2 + 1] + bvals[nt].y;
                if (OUT_MODE == 1) {
                    float2 rr = *(const float2*)&resid[obase + n];
                    vx += rr.x; vy += rr.y;
                }
                if (OUT_HALF) {
                    __half2* op = (__half2*)((__half*)Cout + obase + n);
                    *op = __floats2half2_rn(vx, vy);
                } else {
                    *(float2*)((float*)Cout + obase + n) = make_float2(vx, vy);
                }
            }
        }
    }
}

// ---------------------------------------------------------------------------
// Fused softmax + bilinear sampling — 2 queries/warp, 4 points in parallel,
// 8 channels per lane (LDG.128), per-level HFMA2 corner accumulation.
// __launch_bounds__(512, 3): cap regs at 42 so 3 blocks/SM (48 warps, 75% occ).
// ---------------------------------------------------------------------------
#define SHFL16(v, s) __shfl_sync(0xffffffffu, (v), (s), 16)

__device__ __forceinline__ void corner_acc_h2(__half2 (&hacc)[4], const uint4* p,
                                              __half2 w) {
    uint4 u = *p;
    hacc[0] = __hfma2(*reinterpret_cast<__half2*>(&u.x), w, hacc[0]);
    hacc[1] = __hfma2(*reinterpret_cast<__half2*>(&u.y), w, hacc[1]);
    hacc[2] = __hfma2(*reinterpret_cast<__half2*>(&u.z), w, hacc[2]);
    hacc[3] = __hfma2(*reinterpret_cast<__half2*>(&u.w), w, hacc[3]);
}

__global__ __launch_bounds__(512, 3)
void msda_sample(const float* __restrict__ rp,
                 const __half* __restrict__ val,
                 const __half* __restrict__ proj,
                 __half* __restrict__ msda)
{
    const int gw   = (blockIdx.x * 512 + threadIdx.x) >> 5;
    const int lane = threadIdx.x & 31;
    const int pair = gw >> 3;
    const int h    = gw & 7;
    const int hl   = lane & 15;            // lane within query-half
    const int bq   = pair * 2 + (lane >> 4);
    const int g4   = hl >> 2;              // 0..3 point group
    const int cq   = hl & 3;               // channel octet (8 ch)
    const int b    = bq / LQc;

    const __half* prow = proj + bq * PROJW;
    float off0 = __half2float(prow[h * 32 + hl]);        // offsets 0..15
    float off1 = __half2float(prow[h * 32 + 16 + hl]);   // offsets 16..31
    float lg   = __half2float(prow[256 + h * 16 + hl]);  // 16 logits
    float rpv  = 0.f;
    if (hl < 8) {
        rpv = rp[bq * (Lc * 2) + hl];
        rpv = fminf(fmaxf(rpv, 1e-5f), 1.f - 1e-5f);
    }

    // Softmax over 16 logits (xor 1..8 stays within each 16-lane half)
    float mx = lg;
    #pragma unroll
    for (int o = 8; o > 0; o >>= 1)
        mx = fmaxf(mx, __shfl_xor_sync(0xffffffffu, mx, o));
    float e = __expf(lg - mx);
    float sum = e;
    #pragma unroll
    for (int o = 8; o > 0; o >>= 1)
        sum += __shfl_xor_sync(0xffffffffu, sum, o);
    float attn_val = e / sum;

    constexpr int HH[4] = {100, 50, 25, 13};
    constexpr int ST[4] = {0, 10000, 12500, 13125};

    // uint4 units: 256 halves/pixel = 32 uint4; lane covers 8 channels
    const uint4* vb = (const uint4*)val + (b * LVc) * 32 + h * 4 + cq;

    float acc[8];
    #pragma unroll
    for (int j = 0; j < 8; j++) acc[j] = 0.f;

    #pragma unroll
    for (int l = 0; l < Lc; l++) {
        const int   Wl = HH[l];
        const int   st = ST[l];
        const float fW = (float)HH[l];

        float rpx = SHFL16(rpv, 2 * l);
        float rpy = SHFL16(rpv, 2 * l + 1);

        const int oidx = l * 8 + 2 * g4;   // offset-pair index for this point
        float offx, offy;
        if (l < 2) { offx = SHFL16(off0, oidx);      offy = SHFL16(off0, oidx + 1); }
        else       { offx = SHFL16(off1, oidx - 16); offy = SHFL16(off1, oidx - 15); }
        float a = SHFL16(attn_val, l * 4 + g4);

        float x = fmaf(rpx, fW, offx) - 0.5f;
        float y = fmaf(rpy, fW, offy) - 0.5f;
        float x0f = floorf(x), y0f = floorf(y);
        int x0 = (int)x0f, y0 = (int)y0f;
        float wx = x - x0f, wy = y - y0f;

        float w00 = a * (1.f - wy) * (1.f - wx);
        float w01 = a * (1.f - wy) * wx;
        float w10 = a * wy * (1.f - wx);
        float w11 = a * wy * wx;

        int x1 = x0 + 1, y1 = y0 + 1;
        bool vx0 = (x0 >= 0) & (x0 < Wl);
        bool vx1 = (x1 >= 0) & (x1 < Wl);
        bool vy0 = (y0 >= 0) & (y0 < Wl);
        bool vy1 = (y1 >= 0) & (y1 < Wl);

        int row0 = (st + y0 * Wl) * 32;
        int row1 = row0 + Wl * 32;

        // Per-level fp16 corner accumulation (4 HFMA2 per corner)
        __half2 hz = __float2half2_rn(0.f);
        __half2 hacc[4] = {hz, hz, hz, hz};
        if (vy0 & vx0) corner_acc_h2(hacc, vb + row0 + x0 * 32, __float2half2_rn(w00));
        if (vy0 & vx1) corner_acc_h2(hacc, vb + row0 + x1 * 32, __float2half2_rn(w01));
        if (vy1 & vx0) corner_acc_h2(hacc, vb + row1 + x0 * 32, __float2half2_rn(w10));
        if (vy1 & vx1) corner_acc_h2(hacc, vb + row1 + x1 * 32, __float2half2_rn(w11));

        // Fold level partial into fp32 master accumulator
        #pragma unroll
        for (int j = 0; j < 4; j++) {
            float2 t = __half22float2(hacc[j]);
            acc[2 * j]     += t.x;
            acc[2 * j + 1] += t.y;
        }
    }

    // Reduce across the 4 point-groups (hl bits 2,3 -> xor 4, xor 8)
    #pragma unroll
    for (int j = 0; j < 8; j++) {
        acc[j] += __shfl_xor_sync(0xffffffffu, acc[j], 4);
        acc[j] += __shfl_xor_sync(0xffffffffu, acc[j], 8);
    }

    if (g4 == 0) {
        uint4 o;
        o.x = pack_h2(acc[0], acc[1]);
        o.y = pack_h2(acc[2], acc[3]);
        o.z = pack_h2(acc[4], acc[5]);
        o.w = pack_h2(acc[6], acc[7]);
        ((uint4*)msda)[bq * 32 + h * 4 + cq] = o;
    }
}

// ---------------------------------------------------------------------------
extern "C" void kernel_launch(void* const* d_in, const int* in_sizes, int n_in,
                              void* d_out, int out_size)
{
    const float* query = (const float*)d_in[0];   // (LQ, B, C)
    const float* rp    = (const float*)d_in[1];   // (B, LQ, L, 2)
    const float* value = (const float*)d_in[2];   // (LV, B, C)
    const float* Wv    = (const float*)d_in[5];
    const float* bv    = (const float*)d_in[6];
    const float* Woff  = (const float*)d_in[7];
    const float* boff  = (const float*)d_in[8];
    const float* Wattn = (const float*)d_in[9];
    const float* battn = (const float*)d_in[10];
    const float* Wo    = (const float*)d_in[11];
    const float* bo    = (const float*)d_in[12];
    float* out = (float*)d_out;

    __half *valp, *msdap, *projp;
    float *wcatp, *bcatp;
    cudaGetSymbolAddress((void**)&valp,  g_val);
    cudaGetSymbolAddress((void**)&projp, g_proj);
    cudaGetSymbolAddress((void**)&msdap, g_msda);
    cudaGetSymbolAddress((void**)&wcatp, g_wcat);
    cudaGetSymbolAddress((void**)&bcatp, g_bcat);

    const int gm = (Mrows + 127) / 128;   // 208

    // 0) concat Woff||Wattn, boff||battn
    concat_w<<<(Cc * PROJW + 255) / 256, 256>>>(Woff, boff, Wattn, battn,
                                                wcatp, bcatp);
    // 1) value projection -> fp16 g_val
    hgemm_tc<true, 0, true, false><<<dim3(gm, 2), 256>>>(
        value, Wv, bv, valp, Mrows, LVc, 256, 256, nullptr);
    // 2) fused offset+attn projection -> fp16 g_proj
    hgemm_tc<true, 0, true, false><<<dim3(gm, 3), 256>>>(
        query, wcatp, bcatp, projp, Mrows, LQc, PROJW, PROJW, nullptr);
    // 3) softmax + bilinear sampling -> fp16 g_msda (2 queries per warp)
    msda_sample<<<(Mrows / 2 * NHc) / 16, 512>>>(rp, valp, projp, msdap);
    // 4) output projection + bias + residual -> d_out (A in fp16)
    hgemm_tc<false, 1, false, true><<<dim3(gm, 2), 256>>>(
        msdap, Wo, bo, out, Mrows, LQc, 256, 256, query);
}